// round 5
// baseline (speedup 1.0000x reference)
#include <cuda_runtime.h>

#define Nn 40000
#define NPAD 40064
#define Mm 10000
#define NNZv 400000
#define FT 128
#define HID 256
#define NCLS 10
#define NG 128
#define BN_EPS 1e-5f

// ---------------- scratch ----------------
__device__ float g_E[(size_t)Mm * HID];
__device__ float g_P0[(size_t)NPAD * HID];   // H(Ht(bn(h0))): layer1 input AND pooled h0
__device__ float g_P1[(size_t)NPAD * HID];   // pooled h1; reused as Pa [N,128] in layer0
__device__ float g_Z[(size_t)NPAD * HID];
__device__ float g_h0[(size_t)NPAD * HID];
__device__ float g_h1[(size_t)NPAD * HID];
__device__ float g_dinv[Nn];
__device__ float g_stats[2 * HID];
__device__ float g_bn[2 * HID];              // sc | sh
__device__ float g_out[(size_t)Nn * NCLS];
__device__ float g_segsum[NG * NCLS];
__device__ float g_segcnt[NG];
__device__ int g_ecnt[Mm];
__device__ int g_estart[Mm + 1];
__device__ int g_ecur[Mm];
__device__ int g_elist[NNZv];
__device__ int g_ncnt[Nn];
__device__ int g_nstart[Nn + 1];
__device__ int g_ncur[Nn];
__device__ int g_nlist[NNZv];

// ---------------- init / utility ----------------
__global__ void k_init(int* ecnt, int* ncnt, float* stats) {
    int i = blockIdx.x * blockDim.x + threadIdx.x;
    int stride = gridDim.x * blockDim.x;
    for (int j = i; j < Mm; j += stride) ecnt[j] = 0;
    for (int j = i; j < Nn; j += stride) ncnt[j] = 0;
    if (i < 2 * HID) stats[i] = 0.f;
}
__global__ void k_zerof(float* p, int n) {
    int i = blockIdx.x * blockDim.x + threadIdx.x;
    if (i < n) p[i] = 0.f;
}

// ---------------- CSR build ----------------
__global__ void k_hist(const int* __restrict__ nidx, const int* __restrict__ eidx,
                       int* __restrict__ ecnt, int* __restrict__ ncnt) {
    int i = blockIdx.x * blockDim.x + threadIdx.x;
    if (i < NNZv) {
        atomicAdd(&ecnt[eidx[i]], 1);
        atomicAdd(&ncnt[nidx[i]], 1);
    }
}

__global__ void k_scan2(const int* __restrict__ ecnt, int* __restrict__ estart, int* __restrict__ ecur,
                        const int* __restrict__ ncnt, int* __restrict__ nstart, int* __restrict__ ncur) {
    const int* cnt = blockIdx.x ? ncnt : ecnt;
    int* start = blockIdx.x ? nstart : estart;
    int* cursor = blockIdx.x ? ncur : ecur;
    int n = blockIdx.x ? Nn : Mm;
    __shared__ int buf[1024];
    __shared__ int carry;
    int t = threadIdx.x;
    if (t == 0) carry = 0;
    __syncthreads();
    for (int base = 0; base < n; base += 1024) {
        int v = (base + t < n) ? cnt[base + t] : 0;
        buf[t] = v;
        __syncthreads();
        for (int off = 1; off < 1024; off <<= 1) {
            int x = (t >= off) ? buf[t - off] : 0;
            __syncthreads();
            buf[t] += x;
            __syncthreads();
        }
        int excl = buf[t] - v + carry;
        if (base + t < n) { start[base + t] = excl; cursor[base + t] = excl; }
        __syncthreads();
        if (t == 1023) carry += buf[1023];
        __syncthreads();
    }
    if (t == 0) start[n] = carry;
}

__global__ void k_fill(const int* __restrict__ nidx, const int* __restrict__ eidx,
                       int* __restrict__ ecur, int* __restrict__ elist,
                       int* __restrict__ ncur, int* __restrict__ nlist) {
    int i = blockIdx.x * blockDim.x + threadIdx.x;
    if (i < NNZv) {
        int e = eidx[i], n = nidx[i];
        elist[atomicAdd(&ecur[e], 1)] = n;
        nlist[atomicAdd(&ncur[n], 1)] = e;
    }
}

__global__ void k_dinv(const int* __restrict__ nstart, const int* __restrict__ nlist,
                       const int* __restrict__ estart, float* __restrict__ dinv) {
    int n = blockIdx.x * blockDim.x + threadIdx.x;
    if (n >= Nn) return;
    int s = nstart[n], e = nstart[n + 1];
    float sum = 0.f;
    for (int j = s; j < e; j++) {
        int ed = nlist[j];
        sum += (float)(estart[ed + 1] - estart[ed]);
    }
    dinv[n] = (sum > 0.f) ? 1.f / sum : 1.f;
}

// ---------------- CSR segment-sum gather ----------------
template <int D>
__global__ void k_gather(const float4* __restrict__ src, const int* __restrict__ start,
                         const int* __restrict__ list, float4* __restrict__ dst, int rows) {
    constexpr int WPR = D / 128;
    int gw = (blockIdx.x * blockDim.x + threadIdx.x) >> 5;
    int lane = threadIdx.x & 31;
    int row = gw / WPR;
    if (row >= rows) return;
    int col = (gw % WPR) * 32 + lane;
    int s = __ldg(&start[row]), e = __ldg(&start[row + 1]);
    float4 acc = make_float4(0.f, 0.f, 0.f, 0.f);
    for (int j0 = s; j0 < e; j0 += 32) {
        int cnt = min(32, e - j0);
        int id = 0;
        if (lane < cnt) id = __ldg(&list[j0 + lane]);
        for (int jj = 0; jj < cnt; jj++) {
            int r = __shfl_sync(0xffffffffu, id, jj);
            float4 v = __ldg(&src[(size_t)r * (D / 4) + col]);
            acc.x += v.x; acc.y += v.y; acc.z += v.z; acc.w += v.w;
        }
    }
    dst[(size_t)row * (D / 4) + col] = acc;
}

// gather with on-the-fly BN+relu applied to src rows (D=256)
__global__ void k_gather_bn(const float4* __restrict__ src, const int* __restrict__ start,
                            const int* __restrict__ list, const float* __restrict__ bn,
                            float4* __restrict__ dst, int rows) {
    int gw = (blockIdx.x * blockDim.x + threadIdx.x) >> 5;
    int lane = threadIdx.x & 31;
    int row = gw >> 1;
    if (row >= rows) return;
    int col = ((gw & 1) << 5) + lane;
    float4 sc = ((const float4*)bn)[col];
    float4 sh = ((const float4*)(bn + HID))[col];
    int s = __ldg(&start[row]), e = __ldg(&start[row + 1]);
    float4 acc = make_float4(0.f, 0.f, 0.f, 0.f);
    for (int j0 = s; j0 < e; j0 += 32) {
        int cnt = min(32, e - j0);
        int id = 0;
        if (lane < cnt) id = __ldg(&list[j0 + lane]);
        for (int jj = 0; jj < cnt; jj++) {
            int r = __shfl_sync(0xffffffffu, id, jj);
            float4 v = __ldg(&src[(size_t)r * 64 + col]);
            acc.x += fmaxf(v.x * sc.x + sh.x, 0.f);
            acc.y += fmaxf(v.y * sc.y + sh.y, 0.f);
            acc.z += fmaxf(v.z * sc.z + sh.z, 0.f);
            acc.w += fmaxf(v.w * sc.w + sh.w, 0.f);
        }
    }
    dst[(size_t)row * 64 + col] = acc;
}

// ---------------- tf32x3 tensor-core GEMM ----------------
__device__ __forceinline__ unsigned tf32r(float f) {
    unsigned r;
    asm("cvt.rna.tf32.f32 %0, %1;" : "=r"(r) : "f"(f));
    return r;
}
__device__ __forceinline__ void mma8(float* c, const unsigned* a, unsigned b0, unsigned b1) {
    asm volatile(
        "mma.sync.aligned.m16n8k8.row.col.f32.tf32.tf32.f32 "
        "{%0,%1,%2,%3}, {%4,%5,%6,%7}, {%8,%9}, {%0,%1,%2,%3};"
        : "+f"(c[0]), "+f"(c[1]), "+f"(c[2]), "+f"(c[3])
        : "r"(a[0]), "r"(a[1]), "r"(a[2]), "r"(a[3]), "r"(b0), "r"(b1));
}

// C[Mrows x Nc] = act(A) @ B + bias. Block tile 128x128, 256 thr (8 warps, 32x64 each).
// A/B split hi/lo at smem store -> 3 mma passes (hi*hi + lo*hi + hi*lo) ~ fp32 precision.
template <bool BNA>
__global__ __launch_bounds__(256) void k_gemm_tc(
    const float* __restrict__ A, const float* __restrict__ B,
    const float* __restrict__ bias, const float* __restrict__ bn,
    float* __restrict__ C, int K, int Nc, int Mrows) {
    __shared__ unsigned Ah[16][132], Al[16][132];
    __shared__ unsigned Bh[16][132], Bl[16][132];
    const int t = threadIdx.x;
    const int wid = t >> 5, lane = t & 31;
    const int wm = wid & 3, wn = wid >> 2;
    const int row0 = blockIdx.y * 128, col0 = blockIdx.x * 128;

    float acc[2][8][4];
#pragma unroll
    for (int i = 0; i < 2; i++)
#pragma unroll
        for (int j = 0; j < 8; j++)
#pragma unroll
            for (int r = 0; r < 4; r++) acc[i][j][r] = 0.f;

    const int ar = t >> 1;        // A fill: row 0..127
    const int ak = (t & 1) * 8;   // k offset 0/8
    const int bk = t >> 4;        // B fill: k 0..15
    const int bc = (t & 15) * 8;  // col offset

    for (int kb = 0; kb < K; kb += 16) {
        // A 128x16 -> hi/lo
#pragma unroll
        for (int q = 0; q < 2; q++) {
            float4 v = *(const float4*)(A + (size_t)(row0 + ar) * K + kb + ak + q * 4);
            if (BNA) {
                float4 sc = *(const float4*)(bn + kb + ak + q * 4);
                float4 sh = *(const float4*)(bn + HID + kb + ak + q * 4);
                v.x = fmaxf(v.x * sc.x + sh.x, 0.f);
                v.y = fmaxf(v.y * sc.y + sh.y, 0.f);
                v.z = fmaxf(v.z * sc.z + sh.z, 0.f);
                v.w = fmaxf(v.w * sc.w + sh.w, 0.f);
            }
            float vv[4] = {v.x, v.y, v.z, v.w};
#pragma unroll
            for (int j = 0; j < 4; j++) {
                unsigned hi = tf32r(vv[j]);
                float lo = vv[j] - __uint_as_float(hi);
                Ah[ak + q * 4 + j][ar] = hi;
                Al[ak + q * 4 + j][ar] = tf32r(lo);
            }
        }
        // B 16x128 -> hi/lo (contiguous in n)
#pragma unroll
        for (int q = 0; q < 2; q++) {
            float4 v = *(const float4*)(B + (size_t)(kb + bk) * Nc + col0 + bc + q * 4);
            float vv[4] = {v.x, v.y, v.z, v.w};
            unsigned h[4], l[4];
#pragma unroll
            for (int j = 0; j < 4; j++) {
                h[j] = tf32r(vv[j]);
                l[j] = tf32r(vv[j] - __uint_as_float(h[j]));
            }
            *(uint4*)&Bh[bk][bc + q * 4] = make_uint4(h[0], h[1], h[2], h[3]);
            *(uint4*)&Bl[bk][bc + q * 4] = make_uint4(l[0], l[1], l[2], l[3]);
        }
        __syncthreads();

#pragma unroll
        for (int ks = 0; ks < 2; ks++) {
            const int k0 = ks * 8 + (lane & 3);
            const int mb = wm * 32 + (lane >> 2);
            unsigned ah[2][4], al[2][4];
#pragma unroll
            for (int mt = 0; mt < 2; mt++) {
                int m = mb + mt * 16;
                ah[mt][0] = Ah[k0][m];     ah[mt][1] = Ah[k0][m + 8];
                ah[mt][2] = Ah[k0 + 4][m]; ah[mt][3] = Ah[k0 + 4][m + 8];
                al[mt][0] = Al[k0][m];     al[mt][1] = Al[k0][m + 8];
                al[mt][2] = Al[k0 + 4][m]; al[mt][3] = Al[k0 + 4][m + 8];
            }
#pragma unroll
            for (int nt = 0; nt < 8; nt++) {
                int n = wn * 64 + nt * 8 + (lane >> 2);
                unsigned bh0 = Bh[k0][n], bh1 = Bh[k0 + 4][n];
                unsigned bl0 = Bl[k0][n], bl1 = Bl[k0 + 4][n];
#pragma unroll
                for (int mt = 0; mt < 2; mt++) {
                    mma8(acc[mt][nt], ah[mt], bh0, bh1);
                    mma8(acc[mt][nt], al[mt], bh0, bh1);
                    mma8(acc[mt][nt], ah[mt], bl0, bl1);
                }
            }
        }
        __syncthreads();
    }
    // epilogue
#pragma unroll
    for (int mt = 0; mt < 2; mt++) {
#pragma unroll
        for (int nt = 0; nt < 8; nt++) {
            int r = row0 + wm * 32 + mt * 16 + (lane >> 2);
            int c = col0 + wn * 64 + nt * 8 + 2 * (lane & 3);
            float2 bb = *(const float2*)&bias[c];
            if (r < Mrows)
                *(float2*)(C + (size_t)r * Nc + c) =
                    make_float2(acc[mt][nt][0] + bb.x, acc[mt][nt][1] + bb.y);
            if (r + 8 < Mrows)
                *(float2*)(C + (size_t)(r + 8) * Nc + c) =
                    make_float2(acc[mt][nt][2] + bb.x, acc[mt][nt][3] + bb.y);
        }
    }
}

// ---------------- BatchNorm stats + params ----------------
#define BN_ROWS 50
__global__ void k_bnstats(const float* __restrict__ x, float* __restrict__ stats) {
    int c = threadIdx.x;
    int r0 = blockIdx.x * BN_ROWS;
    float s = 0.f, q = 0.f;
#pragma unroll 5
    for (int r = 0; r < BN_ROWS; r++) {
        float v = x[(size_t)(r0 + r) * HID + c];
        s += v;
        q += v * v;
    }
    atomicAdd(&stats[c], s);
    atomicAdd(&stats[HID + c], q);
}

__global__ void k_bnparams(float* __restrict__ stats, const float* __restrict__ g,
                           const float* __restrict__ b, float* __restrict__ bn) {
    int c = threadIdx.x;
    float mean = stats[c] * (1.f / Nn);
    float var = stats[HID + c] * (1.f / Nn) - mean * mean;
    float sc = g[c] * rsqrtf(var + BN_EPS);
    bn[c] = sc;
    bn[HID + c] = b[c] - mean * sc;
    stats[c] = 0.f;
    stats[HID + c] = 0.f;
}

// ---------------- head + readout ----------------
__global__ void k_head(const float* __restrict__ p0, const float* __restrict__ p1,
                       const float* __restrict__ dinv,
                       const float* __restrict__ W, const float* __restrict__ hb,
                       float* __restrict__ out) {
    int wid = (blockIdx.x * blockDim.x + threadIdx.x) >> 5;
    int lane = threadIdx.x & 31;
    if (wid >= Nn) return;
    float acc[NCLS] = {};
    const float* r0 = p0 + (size_t)wid * HID;
    const float* r1 = p1 + (size_t)wid * HID;
    for (int k = lane; k < HID; k += 32) {
        float v = r0[k];
        const float* w = W + (size_t)k * NCLS;
#pragma unroll
        for (int c = 0; c < NCLS; c++) acc[c] += v * w[c];
        float v2 = r1[k];
        const float* w2 = W + (size_t)(HID + k) * NCLS;
#pragma unroll
        for (int c = 0; c < NCLS; c++) acc[c] += v2 * w2[c];
    }
#pragma unroll
    for (int o = 16; o > 0; o >>= 1)
#pragma unroll
        for (int c = 0; c < NCLS; c++) acc[c] += __shfl_down_sync(0xffffffffu, acc[c], o);
    if (lane == 0) {
        float d = dinv[wid];
#pragma unroll
        for (int c = 0; c < NCLS; c++) out[(size_t)wid * NCLS + c] = acc[c] * d + hb[c];
    }
}

__global__ void k_seg(const float* __restrict__ out, const int* __restrict__ batch,
                      float* __restrict__ ssum, float* __restrict__ scnt) {
    int n = blockIdx.x * blockDim.x + threadIdx.x;
    if (n >= Nn) return;
    int b = batch[n];
    atomicAdd(&scnt[b], 1.f);
#pragma unroll
    for (int c = 0; c < NCLS; c++) atomicAdd(&ssum[b * NCLS + c], out[(size_t)n * NCLS + c]);
}

__global__ void k_fin(const float* __restrict__ ssum, const float* __restrict__ scnt,
                      float* __restrict__ dout) {
    int t = blockIdx.x * blockDim.x + threadIdx.x;
    if (t < NG * NCLS) {
        int gidx = t / NCLS;
        dout[t] = ssum[t] / fmaxf(scnt[gidx], 1.f);
    }
}

// ---------------- host ----------------
extern "C" void kernel_launch(void* const* d_in, const int* in_sizes, int n_in,
                              void* d_out, int out_size) {
    const float* X = (const float*)d_in[0];
    const int* node_idx = (const int*)d_in[1];
    const int* edge_idx = (const int*)d_in[2];
    const int* all_batch = (const int*)d_in[3];
    const float* W1_0 = (const float*)d_in[4];
    const float* b1_0 = (const float*)d_in[5];
    const float* g1_0 = (const float*)d_in[6];
    const float* be1_0 = (const float*)d_in[7];
    const float* W2_0 = (const float*)d_in[8];
    const float* b2_0 = (const float*)d_in[9];
    const float* bng_0 = (const float*)d_in[10];
    const float* bnb_0 = (const float*)d_in[11];
    const float* W1_1 = (const float*)d_in[12];
    const float* b1_1 = (const float*)d_in[13];
    const float* g1_1 = (const float*)d_in[14];
    const float* be1_1 = (const float*)d_in[15];
    const float* W2_1 = (const float*)d_in[16];
    const float* b2_1 = (const float*)d_in[17];
    const float* bng_1 = (const float*)d_in[18];
    const float* bnb_1 = (const float*)d_in[19];
    const float* head_W = (const float*)d_in[20];
    const float* head_b = (const float*)d_in[21];

    float *E, *P0, *P1, *Z, *h0, *h1, *dinv, *stats, *bn, *outp, *ssum, *scnt;
    int *ecnt, *estart, *ecur, *elist, *ncnt, *nstart, *ncur, *nlist;
    cudaGetSymbolAddress((void**)&E, g_E);
    cudaGetSymbolAddress((void**)&P0, g_P0);
    cudaGetSymbolAddress((void**)&P1, g_P1);
    cudaGetSymbolAddress((void**)&Z, g_Z);
    cudaGetSymbolAddress((void**)&h0, g_h0);
    cudaGetSymbolAddress((void**)&h1, g_h1);
    cudaGetSymbolAddress((void**)&dinv, g_dinv);
    cudaGetSymbolAddress((void**)&stats, g_stats);
    cudaGetSymbolAddress((void**)&bn, g_bn);
    cudaGetSymbolAddress((void**)&outp, g_out);
    cudaGetSymbolAddress((void**)&ssum, g_segsum);
    cudaGetSymbolAddress((void**)&scnt, g_segcnt);
    cudaGetSymbolAddress((void**)&ecnt, g_ecnt);
    cudaGetSymbolAddress((void**)&estart, g_estart);
    cudaGetSymbolAddress((void**)&ecur, g_ecur);
    cudaGetSymbolAddress((void**)&elist, g_elist);
    cudaGetSymbolAddress((void**)&ncnt, g_ncnt);
    cudaGetSymbolAddress((void**)&nstart, g_nstart);
    cudaGetSymbolAddress((void**)&ncur, g_ncur);
    cudaGetSymbolAddress((void**)&nlist, g_nlist);

    const int SB = 256;
    const int nnz_blocks = (NNZv + SB - 1) / SB;
    const int ge128 = (Mm * 32 + SB - 1) / SB;
    const int gn128 = (Nn * 32 + SB - 1) / SB;
    const int ge256 = (Mm * 64 + SB - 1) / SB;
    const int gn256 = (Nn * 64 + SB - 1) / SB;
    dim3 tc_grid(HID / 128, NPAD / 128);   // (2, 313)

    // ---- CSR build ----
    k_init<<<64, SB>>>(ecnt, ncnt, stats);
    k_hist<<<nnz_blocks, SB>>>(node_idx, edge_idx, ecnt, ncnt);
    k_scan2<<<2, 1024>>>(ecnt, estart, ecur, ncnt, nstart, ncur);
    k_fill<<<nnz_blocks, SB>>>(node_idx, edge_idx, ecur, elist, ncur, nlist);
    k_dinv<<<(Nn + SB - 1) / SB, SB>>>(nstart, nlist, estart, dinv);

    // ---- layer 0 (Pa in P1 buffer, [N,128]) ----
    k_gather<128><<<ge128, SB>>>((const float4*)X, estart, elist, (float4*)E, Mm);
    k_gather<128><<<gn128, SB>>>((const float4*)E, nstart, nlist, (float4*)P1, Nn);
    k_gemm_tc<false><<<tc_grid, 256>>>(P1, W1_0, b1_0, bn, Z, FT, HID, Nn);
    k_bnstats<<<Nn / BN_ROWS, HID>>>(Z, stats);
    k_bnparams<<<1, HID>>>(stats, g1_0, be1_0, bn);
    k_gemm_tc<true><<<tc_grid, 256>>>(Z, W2_0, b2_0, bn, h0, HID, HID, Nn);
    k_bnstats<<<Nn / BN_ROWS, HID>>>(h0, stats);
    k_bnparams<<<1, HID>>>(stats, bng_0, bnb_0, bn);

    // ---- layer 1 (P0 = H(Ht(bn(h0))), reused for head) ----
    k_gather_bn<<<ge256, SB>>>((const float4*)h0, estart, elist, bn, (float4*)E, Mm);
    k_gather<256><<<gn256, SB>>>((const float4*)E, nstart, nlist, (float4*)P0, Nn);
    k_gemm_tc<false><<<tc_grid, 256>>>(P0, W1_1, b1_1, bn, Z, HID, HID, Nn);
    k_bnstats<<<Nn / BN_ROWS, HID>>>(Z, stats);
    k_bnparams<<<1, HID>>>(stats, g1_1, be1_1, bn);
    k_gemm_tc<true><<<tc_grid, 256>>>(Z, W2_1, b2_1, bn, h1, HID, HID, Nn);
    k_bnstats<<<Nn / BN_ROWS, HID>>>(h1, stats);
    k_bnparams<<<1, HID>>>(stats, bng_1, bnb_1, bn);

    // ---- pooling for h1 ----
    k_gather_bn<<<ge256, SB>>>((const float4*)h1, estart, elist, bn, (float4*)E, Mm);
    k_gather<256><<<gn256, SB>>>((const float4*)E, nstart, nlist, (float4*)P1, Nn);

    // ---- head + readout ----
    k_head<<<(Nn * 32 + SB - 1) / SB, SB>>>(P0, P1, dinv, head_W, head_b, outp);
    k_zerof<<<(NG * NCLS + SB - 1) / SB, SB>>>(ssum, NG * NCLS);
    k_zerof<<<1, NG>>>(scnt, NG);
    k_seg<<<(Nn + SB - 1) / SB, SB>>>(outp, all_batch, ssum, scnt);
    k_fin<<<(NG * NCLS + SB - 1) / SB, SB>>>(ssum, scnt, (float*)d_out);
}

// round 6
// speedup vs baseline: 1.0127x; 1.0127x over previous
#include <cuda_runtime.h>
#include <cuda_fp16.h>

#define Nn 40000
#define NPAD 40064
#define Mm 10000
#define NNZv 400000
#define FT 128
#define HID 256
#define NCLS 10
#define NG 128
#define BN_EPS 1e-5f

// ---------------- scratch ----------------
__device__ float g_P0[(size_t)NPAD * HID];   // H(Ht(bn(h0))): layer1 input AND pooled h0
__device__ float g_P1[(size_t)NPAD * HID];   // pooled h1; reused as Pa [N,128] in layer0
__device__ float g_Z[(size_t)NPAD * HID];
__device__ float g_h0[(size_t)NPAD * HID];
__device__ float g_h1[(size_t)NPAD * HID];
__device__ __half g_Xh[(size_t)Nn * FT];     // fp16 X
__device__ __half g_hh[(size_t)Nn * HID];    // fp16 BN'd hidden (reused h0 then h1)
__device__ __half g_Eh[(size_t)Mm * HID];    // fp16 edge accumulator
__device__ float g_dinv[Nn];
__device__ float g_stats[2 * HID];
__device__ float g_bn[2 * HID];              // sc | sh
__device__ float g_out[(size_t)Nn * NCLS];
__device__ float g_segsum[NG * NCLS];
__device__ float g_segcnt[NG];
__device__ int g_ecnt[Mm];
__device__ int g_estart[Mm + 1];
__device__ int g_ecur[Mm];
__device__ int g_elist[NNZv];
__device__ int g_ncnt[Nn];
__device__ int g_nstart[Nn + 1];
__device__ int g_ncur[Nn];
__device__ int g_nlist[NNZv];

// ---------------- init / utility ----------------
__global__ void k_init(int* ecnt, int* ncnt, float* stats) {
    int i = blockIdx.x * blockDim.x + threadIdx.x;
    int stride = gridDim.x * blockDim.x;
    for (int j = i; j < Mm; j += stride) ecnt[j] = 0;
    for (int j = i; j < Nn; j += stride) ncnt[j] = 0;
    if (i < 2 * HID) stats[i] = 0.f;
}
__global__ void k_zerof(float* p, int n) {
    int i = blockIdx.x * blockDim.x + threadIdx.x;
    if (i < n) p[i] = 0.f;
}

// ---------------- CSR build ----------------
__global__ void k_hist(const int* __restrict__ nidx, const int* __restrict__ eidx,
                       int* __restrict__ ecnt, int* __restrict__ ncnt) {
    int i = blockIdx.x * blockDim.x + threadIdx.x;
    if (i < NNZv) {
        atomicAdd(&ecnt[eidx[i]], 1);
        atomicAdd(&ncnt[nidx[i]], 1);
    }
}

__global__ void k_scan2(const int* __restrict__ ecnt, int* __restrict__ estart, int* __restrict__ ecur,
                        const int* __restrict__ ncnt, int* __restrict__ nstart, int* __restrict__ ncur) {
    const int* cnt = blockIdx.x ? ncnt : ecnt;
    int* start = blockIdx.x ? nstart : estart;
    int* cursor = blockIdx.x ? ncur : ecur;
    int n = blockIdx.x ? Nn : Mm;
    __shared__ int buf[1024];
    __shared__ int carry;
    int t = threadIdx.x;
    if (t == 0) carry = 0;
    __syncthreads();
    for (int base = 0; base < n; base += 1024) {
        int v = (base + t < n) ? cnt[base + t] : 0;
        buf[t] = v;
        __syncthreads();
        for (int off = 1; off < 1024; off <<= 1) {
            int x = (t >= off) ? buf[t - off] : 0;
            __syncthreads();
            buf[t] += x;
            __syncthreads();
        }
        int excl = buf[t] - v + carry;
        if (base + t < n) { start[base + t] = excl; cursor[base + t] = excl; }
        __syncthreads();
        if (t == 1023) carry += buf[1023];
        __syncthreads();
    }
    if (t == 0) start[n] = carry;
}

__global__ void k_fill(const int* __restrict__ nidx, const int* __restrict__ eidx,
                       int* __restrict__ ecur, int* __restrict__ elist,
                       int* __restrict__ ncur, int* __restrict__ nlist) {
    int i = blockIdx.x * blockDim.x + threadIdx.x;
    if (i < NNZv) {
        int e = eidx[i], n = nidx[i];
        elist[atomicAdd(&ecur[e], 1)] = n;
        nlist[atomicAdd(&ncur[n], 1)] = e;
    }
}

__global__ void k_dinv(const int* __restrict__ nstart, const int* __restrict__ nlist,
                       const int* __restrict__ estart, float* __restrict__ dinv) {
    int n = blockIdx.x * blockDim.x + threadIdx.x;
    if (n >= Nn) return;
    int s = nstart[n], e = nstart[n + 1];
    float sum = 0.f;
    for (int j = s; j < e; j++) {
        int ed = nlist[j];
        sum += (float)(estart[ed + 1] - estart[ed]);
    }
    dinv[n] = (sum > 0.f) ? 1.f / sum : 1.f;
}

// ---------------- convert helpers ----------------
__device__ __forceinline__ uint4 pack8(const float* f) {
    uint4 u;
    __half2 h0 = __float22half2_rn(make_float2(f[0], f[1]));
    __half2 h1 = __float22half2_rn(make_float2(f[2], f[3]));
    __half2 h2 = __float22half2_rn(make_float2(f[4], f[5]));
    __half2 h3 = __float22half2_rn(make_float2(f[6], f[7]));
    u.x = *(unsigned*)&h0; u.y = *(unsigned*)&h1;
    u.z = *(unsigned*)&h2; u.w = *(unsigned*)&h3;
    return u;
}

// X [N,128] fp32 -> fp16
__global__ void k_cvtX(const float* __restrict__ src, uint4* __restrict__ dst) {
    int i = blockIdx.x * blockDim.x + threadIdx.x;   // octet index
    if (i >= Nn * FT / 8) return;
    float f[8];
    *(float4*)&f[0] = *(const float4*)(src + (size_t)i * 8);
    *(float4*)&f[4] = *(const float4*)(src + (size_t)i * 8 + 4);
    dst[i] = pack8(f);
}

// h [N,256] fp32 + bn -> relu(h*sc+sh) fp16
__global__ void k_bnrelu_cvt(const float* __restrict__ src, const float* __restrict__ bn,
                             uint4* __restrict__ dst) {
    int i = blockIdx.x * blockDim.x + threadIdx.x;   // octet index
    if (i >= Nn * HID / 8) return;
    int c8 = (i & 31) * 8;
    float f[8], sc[8], sh[8];
    *(float4*)&f[0] = *(const float4*)(src + (size_t)i * 8);
    *(float4*)&f[4] = *(const float4*)(src + (size_t)i * 8 + 4);
    *(float4*)&sc[0] = *(const float4*)(bn + c8);
    *(float4*)&sc[4] = *(const float4*)(bn + c8 + 4);
    *(float4*)&sh[0] = *(const float4*)(bn + HID + c8);
    *(float4*)&sh[4] = *(const float4*)(bn + HID + c8 + 4);
#pragma unroll
    for (int j = 0; j < 8; j++) f[j] = fmaxf(f[j] * sc[j] + sh[j], 0.f);
    dst[i] = pack8(f);
}

// ---------------- fp16 CSR segment-sum gather ----------------
// D=256: one warp per row, lane owns 8 channels (one uint4).
// D=128: one warp per row, lanes 0-15 / 16-31 process even/odd neighbors, xor-16 reduce.
template <int D, bool OUT_HALF>
__global__ void k_gath(const uint4* __restrict__ src, const int* __restrict__ start,
                       const int* __restrict__ list, void* __restrict__ dst, int rows) {
    int row = (blockIdx.x * blockDim.x + threadIdx.x) >> 5;
    int lane = threadIdx.x & 31;
    if (row >= rows) return;
    int s = __ldg(&start[row]), e = __ldg(&start[row + 1]);
    float acc[8] = {};
    if (D == 256) {
        for (int j0 = s; j0 < e; j0 += 32) {
            int cnt = min(32, e - j0);
            int id = (lane < cnt) ? __ldg(&list[j0 + lane]) : 0;
            for (int jj = 0; jj < cnt; jj++) {
                int r = __shfl_sync(0xffffffffu, id, jj);
                uint4 v = __ldg(&src[(size_t)r * 32 + lane]);
                const __half2* h = (const __half2*)&v;
#pragma unroll
                for (int q = 0; q < 4; q++) {
                    float2 f = __half22float2(h[q]);
                    acc[2 * q] += f.x;
                    acc[2 * q + 1] += f.y;
                }
            }
        }
    } else {  // D == 128
        int oct = lane & 15, par = lane >> 4;
        for (int j0 = s; j0 < e; j0 += 32) {
            int cnt = min(32, e - j0);
            int id = (lane < cnt) ? __ldg(&list[j0 + lane]) : 0;
            for (int jj = 0; jj < cnt; jj += 2) {
                int r0 = __shfl_sync(0xffffffffu, id, jj);
                int r1 = (jj + 1 < cnt) ? __shfl_sync(0xffffffffu, id, jj + 1) : -1;
                int r = par ? r1 : r0;
                if (r >= 0) {
                    uint4 v = __ldg(&src[(size_t)r * 16 + oct]);
                    const __half2* h = (const __half2*)&v;
#pragma unroll
                    for (int q = 0; q < 4; q++) {
                        float2 f = __half22float2(h[q]);
                        acc[2 * q] += f.x;
                        acc[2 * q + 1] += f.y;
                    }
                }
            }
        }
#pragma unroll
        for (int q = 0; q < 8; q++) acc[q] += __shfl_xor_sync(0xffffffffu, acc[q], 16);
        if (par) return;
        lane = oct;   // write position below uses lane
    }
    const int OC = D / 8;  // uint4 per row
    if (OUT_HALF) {
        ((uint4*)dst)[(size_t)row * OC + lane] = pack8(acc);
    } else {
        float* o = (float*)dst + (size_t)row * D + lane * 8;
        *(float4*)o = *(float4*)&acc[0];
        *(float4*)(o + 4) = *(float4*)&acc[4];
    }
}

// ---------------- tf32x3 tensor-core GEMM + fused BN stats ----------------
__device__ __forceinline__ unsigned tf32r(float f) {
    unsigned r;
    asm("cvt.rna.tf32.f32 %0, %1;" : "=r"(r) : "f"(f));
    return r;
}
__device__ __forceinline__ void mma8(float* c, const unsigned* a, unsigned b0, unsigned b1) {
    asm volatile(
        "mma.sync.aligned.m16n8k8.row.col.f32.tf32.tf32.f32 "
        "{%0,%1,%2,%3}, {%4,%5,%6,%7}, {%8,%9}, {%0,%1,%2,%3};"
        : "+f"(c[0]), "+f"(c[1]), "+f"(c[2]), "+f"(c[3])
        : "r"(a[0]), "r"(a[1]), "r"(a[2]), "r"(a[3]), "r"(b0), "r"(b1));
}

template <bool BNA>
__global__ __launch_bounds__(256) void k_gemm_tc(
    const float* __restrict__ A, const float* __restrict__ B,
    const float* __restrict__ bias, const float* __restrict__ bn,
    float* __restrict__ C, float* __restrict__ stats, int K, int Nc, int Mrows) {
    __shared__ unsigned Ah[16][132], Al[16][132];
    __shared__ unsigned Bh[16][132], Bl[16][132];
    __shared__ float shS[128], shQ[128];
    const int t = threadIdx.x;
    const int wid = t >> 5, lane = t & 31;
    const int wm = wid & 3, wn = wid >> 2;
    const int row0 = blockIdx.y * 128, col0 = blockIdx.x * 128;

    float acc[2][8][4];
#pragma unroll
    for (int i = 0; i < 2; i++)
#pragma unroll
        for (int j = 0; j < 8; j++)
#pragma unroll
            for (int r = 0; r < 4; r++) acc[i][j][r] = 0.f;

    const int ar = t >> 1;
    const int ak = (t & 1) * 8;
    const int bk = t >> 4;
    const int bc = (t & 15) * 8;

    for (int kb = 0; kb < K; kb += 16) {
#pragma unroll
        for (int q = 0; q < 2; q++) {
            float4 v = *(const float4*)(A + (size_t)(row0 + ar) * K + kb + ak + q * 4);
            if (BNA) {
                float4 sc = *(const float4*)(bn + kb + ak + q * 4);
                float4 sh = *(const float4*)(bn + HID + kb + ak + q * 4);
                v.x = fmaxf(v.x * sc.x + sh.x, 0.f);
                v.y = fmaxf(v.y * sc.y + sh.y, 0.f);
                v.z = fmaxf(v.z * sc.z + sh.z, 0.f);
                v.w = fmaxf(v.w * sc.w + sh.w, 0.f);
            }
            float vv[4] = {v.x, v.y, v.z, v.w};
#pragma unroll
            for (int j = 0; j < 4; j++) {
                unsigned hi = tf32r(vv[j]);
                float lo = vv[j] - __uint_as_float(hi);
                Ah[ak + q * 4 + j][ar] = hi;
                Al[ak + q * 4 + j][ar] = tf32r(lo);
            }
        }
#pragma unroll
        for (int q = 0; q < 2; q++) {
            float4 v = *(const float4*)(B + (size_t)(kb + bk) * Nc + col0 + bc + q * 4);
            float vv[4] = {v.x, v.y, v.z, v.w};
            unsigned h[4], l[4];
#pragma unroll
            for (int j = 0; j < 4; j++) {
                h[j] = tf32r(vv[j]);
                l[j] = tf32r(vv[j] - __uint_as_float(h[j]));
            }
            *(uint4*)&Bh[bk][bc + q * 4] = make_uint4(h[0], h[1], h[2], h[3]);
            *(uint4*)&Bl[bk][bc + q * 4] = make_uint4(l[0], l[1], l[2], l[3]);
        }
        __syncthreads();

#pragma unroll
        for (int ks = 0; ks < 2; ks++) {
            const int k0 = ks * 8 + (lane & 3);
            const int mb = wm * 32 + (lane >> 2);
            unsigned ah[2][4], al[2][4];
#pragma unroll
            for (int mt = 0; mt < 2; mt++) {
                int m = mb + mt * 16;
                ah[mt][0] = Ah[k0][m];     ah[mt][1] = Ah[k0][m + 8];
                ah[mt][2] = Ah[k0 + 4][m]; ah[mt][3] = Ah[k0 + 4][m + 8];
                al[mt][0] = Al[k0][m];     al[mt][1] = Al[k0][m + 8];
                al[mt][2] = Al[k0 + 4][m]; al[mt][3] = Al[k0 + 4][m + 8];
            }
#pragma unroll
            for (int nt = 0; nt < 8; nt++) {
                int n = wn * 64 + nt * 8 + (lane >> 2);
                unsigned bh0 = Bh[k0][n], bh1 = Bh[k0 + 4][n];
                unsigned bl0 = Bl[k0][n], bl1 = Bl[k0 + 4][n];
#pragma unroll
                for (int mt = 0; mt < 2; mt++) {
                    mma8(acc[mt][nt], ah[mt], bh0, bh1);
                    mma8(acc[mt][nt], al[mt], bh0, bh1);
                    mma8(acc[mt][nt], ah[mt], bl0, bl1);
                }
            }
        }
        __syncthreads();
    }

    // ---- epilogue: write C + accumulate BN stats (valid rows only) ----
    if (t < 128) { shS[t] = 0.f; shQ[t] = 0.f; }
    __syncthreads();

    float colS[16] = {}, colQ[16] = {};
#pragma unroll
    for (int nt = 0; nt < 8; nt++) {
        int c = col0 + wn * 64 + nt * 8 + 2 * (lane & 3);
        float2 bb = *(const float2*)&bias[c];
#pragma unroll
        for (int mt = 0; mt < 2; mt++) {
            int r = row0 + wm * 32 + mt * 16 + (lane >> 2);
            float v0 = acc[mt][nt][0] + bb.x, v1 = acc[mt][nt][1] + bb.y;
            float v2 = acc[mt][nt][2] + bb.x, v3 = acc[mt][nt][3] + bb.y;
            if (r < Mrows) {
                *(float2*)(C + (size_t)r * Nc + c) = make_float2(v0, v1);
                colS[nt * 2] += v0; colQ[nt * 2] += v0 * v0;
                colS[nt * 2 + 1] += v1; colQ[nt * 2 + 1] += v1 * v1;
            }
            if (r + 8 < Mrows) {
                *(float2*)(C + (size_t)(r + 8) * Nc + c) = make_float2(v2, v3);
                colS[nt * 2] += v2; colQ[nt * 2] += v2 * v2;
                colS[nt * 2 + 1] += v3; colQ[nt * 2 + 1] += v3 * v3;
            }
        }
    }
#pragma unroll
    for (int off = 4; off <= 16; off <<= 1)
#pragma unroll
        for (int i = 0; i < 16; i++) {
            colS[i] += __shfl_xor_sync(0xffffffffu, colS[i], off);
            colQ[i] += __shfl_xor_sync(0xffffffffu, colQ[i], off);
        }
    if ((lane >> 2) == 0) {
#pragma unroll
        for (int i = 0; i < 16; i++) {
            int cc = wn * 64 + (i >> 1) * 8 + 2 * (lane & 3) + (i & 1);
            atomicAdd(&shS[cc], colS[i]);
            atomicAdd(&shQ[cc], colQ[i]);
        }
    }
    __syncthreads();
    if (t < 128) {
        atomicAdd(&stats[col0 + t], shS[t]);
        atomicAdd(&stats[HID + col0 + t], shQ[t]);
    }
}

// ---------------- BN params (consumes + re-zeroes stats) ----------------
__global__ void k_bnparams(float* __restrict__ stats, const float* __restrict__ g,
                           const float* __restrict__ b, float* __restrict__ bn) {
    int c = threadIdx.x;
    float mean = stats[c] * (1.f / Nn);
    float var = stats[HID + c] * (1.f / Nn) - mean * mean;
    float sc = g[c] * rsqrtf(var + BN_EPS);
    bn[c] = sc;
    bn[HID + c] = b[c] - mean * sc;
    stats[c] = 0.f;
    stats[HID + c] = 0.f;
}

// ---------------- head + readout ----------------
__global__ void k_head(const float* __restrict__ p0, const float* __restrict__ p1,
                       const float* __restrict__ dinv,
                       const float* __restrict__ W, const float* __restrict__ hb,
                       float* __restrict__ out) {
    int wid = (blockIdx.x * blockDim.x + threadIdx.x) >> 5;
    int lane = threadIdx.x & 31;
    if (wid >= Nn) return;
    float acc[NCLS] = {};
    const float* r0 = p0 + (size_t)wid * HID;
    const float* r1 = p1 + (size_t)wid * HID;
    for (int k = lane; k < HID; k += 32) {
        float v = r0[k];
        const float* w = W + (size_t)k * NCLS;
#pragma unroll
        for (int c = 0; c < NCLS; c++) acc[c] += v * w[c];
        float v2 = r1[k];
        const float* w2 = W + (size_t)(HID + k) * NCLS;
#pragma unroll
        for (int c = 0; c < NCLS; c++) acc[c] += v2 * w2[c];
    }
#pragma unroll
    for (int o = 16; o > 0; o >>= 1)
#pragma unroll
        for (int c = 0; c < NCLS; c++) acc[c] += __shfl_down_sync(0xffffffffu, acc[c], o);
    if (lane == 0) {
        float d = dinv[wid];
#pragma unroll
        for (int c = 0; c < NCLS; c++) out[(size_t)wid * NCLS + c] = acc[c] * d + hb[c];
    }
}

__global__ void k_seg(const float* __restrict__ out, const int* __restrict__ batch,
                      float* __restrict__ ssum, float* __restrict__ scnt) {
    int n = blockIdx.x * blockDim.x + threadIdx.x;
    if (n >= Nn) return;
    int b = batch[n];
    atomicAdd(&scnt[b], 1.f);
#pragma unroll
    for (int c = 0; c < NCLS; c++) atomicAdd(&ssum[b * NCLS + c], out[(size_t)n * NCLS + c]);
}

__global__ void k_fin(const float* __restrict__ ssum, const float* __restrict__ scnt,
                      float* __restrict__ dout) {
    int t = blockIdx.x * blockDim.x + threadIdx.x;
    if (t < NG * NCLS) {
        int gidx = t / NCLS;
        dout[t] = ssum[t] / fmaxf(scnt[gidx], 1.f);
    }
}

// ---------------- host ----------------
extern "C" void kernel_launch(void* const* d_in, const int* in_sizes, int n_in,
                              void* d_out, int out_size) {
    const float* X = (const float*)d_in[0];
    const int* node_idx = (const int*)d_in[1];
    const int* edge_idx = (const int*)d_in[2];
    const int* all_batch = (const int*)d_in[3];
    const float* W1_0 = (const float*)d_in[4];
    const float* b1_0 = (const float*)d_in[5];
    const float* g1_0 = (const float*)d_in[6];
    const float* be1_0 = (const float*)d_in[7];
    const float* W2_0 = (const float*)d_in[8];
    const float* b2_0 = (const float*)d_in[9];
    const float* bng_0 = (const float*)d_in[10];
    const float* bnb_0 = (const float*)d_in[11];
    const float* W1_1 = (const float*)d_in[12];
    const float* b1_1 = (const float*)d_in[13];
    const float* g1_1 = (const float*)d_in[14];
    const float* be1_1 = (const float*)d_in[15];
    const float* W2_1 = (const float*)d_in[16];
    const float* b2_1 = (const float*)d_in[17];
    const float* bng_1 = (const float*)d_in[18];
    const float* bnb_1 = (const float*)d_in[19];
    const float* head_W = (const float*)d_in[20];
    const float* head_b = (const float*)d_in[21];

    float *P0, *P1, *Z, *h0, *h1, *dinv, *stats, *bn, *outp, *ssum, *scnt;
    __half *Xh, *hh, *Eh;
    int *ecnt, *estart, *ecur, *elist, *ncnt, *nstart, *ncur, *nlist;
    cudaGetSymbolAddress((void**)&P0, g_P0);
    cudaGetSymbolAddress((void**)&P1, g_P1);
    cudaGetSymbolAddress((void**)&Z, g_Z);
    cudaGetSymbolAddress((void**)&h0, g_h0);
    cudaGetSymbolAddress((void**)&h1, g_h1);
    cudaGetSymbolAddress((void**)&Xh, g_Xh);
    cudaGetSymbolAddress((void**)&hh, g_hh);
    cudaGetSymbolAddress((void**)&Eh, g_Eh);
    cudaGetSymbolAddress((void**)&dinv, g_dinv);
    cudaGetSymbolAddress((void**)&stats, g_stats);
    cudaGetSymbolAddress((void**)&bn, g_bn);
    cudaGetSymbolAddress((void**)&outp, g_out);
    cudaGetSymbolAddress((void**)&ssum, g_segsum);
    cudaGetSymbolAddress((void**)&scnt, g_segcnt);
    cudaGetSymbolAddress((void**)&ecnt, g_ecnt);
    cudaGetSymbolAddress((void**)&estart, g_estart);
    cudaGetSymbolAddress((void**)&ecur, g_ecur);
    cudaGetSymbolAddress((void**)&elist, g_elist);
    cudaGetSymbolAddress((void**)&ncnt, g_ncnt);
    cudaGetSymbolAddress((void**)&nstart, g_nstart);
    cudaGetSymbolAddress((void**)&ncur, g_ncur);
    cudaGetSymbolAddress((void**)&nlist, g_nlist);

    const int SB = 256;
    const int nnz_blocks = (NNZv + SB - 1) / SB;
    const int ge = (Mm * 32 + SB - 1) / SB;       // one warp per edge row
    const int gn = (Nn * 32 + SB - 1) / SB;       // one warp per node row
    dim3 tc_grid(HID / 128, NPAD / 128);

    // ---- CSR build ----
    k_init<<<64, SB>>>(ecnt, ncnt, stats);
    k_hist<<<nnz_blocks, SB>>>(node_idx, edge_idx, ecnt, ncnt);
    k_scan2<<<2, 1024>>>(ecnt, estart, ecur, ncnt, nstart, ncur);
    k_fill<<<nnz_blocks, SB>>>(node_idx, edge_idx, ecur, elist, ncur, nlist);
    k_dinv<<<(Nn + SB - 1) / SB, SB>>>(nstart, nlist, estart, dinv);

    // ---- layer 0 (Pa in P1 buffer, [N,128]) ----
    k_cvtX<<<(Nn * FT / 8 + SB - 1) / SB, SB>>>(X, (uint4*)Xh);
    k_gath<128, true><<<ge, SB>>>((const uint4*)Xh, estart, elist, Eh, Mm);
    k_gath<128, false><<<gn, SB>>>((const uint4*)Eh, nstart, nlist, P1, Nn);
    k_gemm_tc<false><<<tc_grid, 256>>>(P1, W1_0, b1_0, bn, Z, stats, FT, HID, Nn);
    k_bnparams<<<1, HID>>>(stats, g1_0, be1_0, bn);
    k_gemm_tc<true><<<tc_grid, 256>>>(Z, W2_0, b2_0, bn, h0, stats, HID, HID, Nn);
    k_bnparams<<<1, HID>>>(stats, bng_0, bnb_0, bn);

    // ---- layer 1 (P0 = H(Ht(bn(h0))), reused for head) ----
    k_bnrelu_cvt<<<(Nn * HID / 8 + SB - 1) / SB, SB>>>(h0, bn, (uint4*)hh);
    k_gath<256, true><<<ge, SB>>>((const uint4*)hh, estart, elist, Eh, Mm);
    k_gath<256, false><<<gn, SB>>>((const uint4*)Eh, nstart, nlist, P0, Nn);
    k_gemm_tc<false><<<tc_grid, 256>>>(P0, W1_1, b1_1, bn, Z, stats, HID, HID, Nn);
    k_bnparams<<<1, HID>>>(stats, g1_1, be1_1, bn);
    k_gemm_tc<true><<<tc_grid, 256>>>(Z, W2_1, b2_1, bn, h1, stats, HID, HID, Nn);
    k_bnparams<<<1, HID>>>(stats, bng_1, bnb_1, bn);

    // ---- pooling for h1 ----
    k_bnrelu_cvt<<<(Nn * HID / 8 + SB - 1) / SB, SB>>>(h1, bn, (uint4*)hh);
    k_gath<256, true><<<ge, SB>>>((const uint4*)hh, estart, elist, Eh, Mm);
    k_gath<256, false><<<gn, SB>>>((const uint4*)Eh, nstart, nlist, P1, Nn);

    // ---- head + readout ----
    k_head<<<(Nn * 32 + SB - 1) / SB, SB>>>(P0, P1, dinv, head_W, head_b, outp);
    k_zerof<<<(NG * NCLS + SB - 1) / SB, SB>>>(ssum, NG * NCLS);
    k_zerof<<<1, NG>>>(scnt, NG);
    k_seg<<<(Nn + SB - 1) / SB, SB>>>(outp, all_batch, ssum, scnt);
    k_fin<<<(NG * NCLS + SB - 1) / SB, SB>>>(ssum, scnt, (float*)d_out);
}

// round 7
// speedup vs baseline: 1.2355x; 1.2200x over previous
#include <cuda_runtime.h>
#include <cuda_fp16.h>
#include <cuda_bf16.h>

#define Nn 40000
#define NPAD 40064
#define Mm 10000
#define NNZv 400000
#define FT 128
#define HID 256
#define NCLS 10
#define NG 128
#define BN_EPS 1e-5f

// ---------------- scratch ----------------
__device__ float g_P0[(size_t)NPAD * HID];
__device__ float g_P1[(size_t)NPAD * HID];
__device__ float g_Z[(size_t)NPAD * HID];
__device__ float g_h0[(size_t)NPAD * HID];
__device__ float g_h1[(size_t)NPAD * HID];
__device__ __half g_Xh[(size_t)Nn * FT];
__device__ __half g_hh[(size_t)Nn * HID];
__device__ __half g_Eh[(size_t)Mm * HID];
__device__ float g_dinv[Nn];
__device__ float g_stats[2 * HID];
__device__ float g_bn[2 * HID];
__device__ float g_segsum[NG * NCLS];
__device__ float g_segcnt[NG];
__device__ int g_ecnt[Mm];
__device__ int g_estart[Mm + 1];
__device__ int g_ecur[Mm];
__device__ int g_elist[NNZv];
__device__ int g_ncnt[Nn];
__device__ int g_nstart[Nn + 1];
__device__ int g_ncur[Nn];
__device__ int g_nlist[NNZv];

// ---------------- init / utility ----------------
__global__ void k_init(int* ecnt, int* ncnt, float* stats, float* ssum, float* scnt) {
    int i = blockIdx.x * blockDim.x + threadIdx.x;
    int stride = gridDim.x * blockDim.x;
    for (int j = i; j < Mm; j += stride) ecnt[j] = 0;
    for (int j = i; j < Nn; j += stride) ncnt[j] = 0;
    if (i < 2 * HID) stats[i] = 0.f;
    if (i < NG * NCLS) ssum[i] = 0.f;
    if (i < NG) scnt[i] = 0.f;
}

// ---------------- CSR build ----------------
__global__ void k_hist(const int* __restrict__ nidx, const int* __restrict__ eidx,
                       int* __restrict__ ecnt, int* __restrict__ ncnt) {
    int i = blockIdx.x * blockDim.x + threadIdx.x;
    if (i < NNZv) {
        atomicAdd(&ecnt[eidx[i]], 1);
        atomicAdd(&ncnt[nidx[i]], 1);
    }
}

__global__ void k_scan2(const int* __restrict__ ecnt, int* __restrict__ estart, int* __restrict__ ecur,
                        const int* __restrict__ ncnt, int* __restrict__ nstart, int* __restrict__ ncur) {
    const int* cnt = blockIdx.x ? ncnt : ecnt;
    int* start = blockIdx.x ? nstart : estart;
    int* cursor = blockIdx.x ? ncur : ecur;
    int n = blockIdx.x ? Nn : Mm;
    __shared__ int buf[1024];
    __shared__ int carry;
    int t = threadIdx.x;
    if (t == 0) carry = 0;
    __syncthreads();
    for (int base = 0; base < n; base += 1024) {
        int v = (base + t < n) ? cnt[base + t] : 0;
        buf[t] = v;
        __syncthreads();
        for (int off = 1; off < 1024; off <<= 1) {
            int x = (t >= off) ? buf[t - off] : 0;
            __syncthreads();
            buf[t] += x;
            __syncthreads();
        }
        int excl = buf[t] - v + carry;
        if (base + t < n) { start[base + t] = excl; cursor[base + t] = excl; }
        __syncthreads();
        if (t == 1023) carry += buf[1023];
        __syncthreads();
    }
    if (t == 0) start[n] = carry;
}

__global__ void k_fill(const int* __restrict__ nidx, const int* __restrict__ eidx,
                       int* __restrict__ ecur, int* __restrict__ elist,
                       int* __restrict__ ncur, int* __restrict__ nlist) {
    int i = blockIdx.x * blockDim.x + threadIdx.x;
    if (i < NNZv) {
        int e = eidx[i], n = nidx[i];
        elist[atomicAdd(&ecur[e], 1)] = n;
        nlist[atomicAdd(&ncur[n], 1)] = e;
    }
}

__global__ void k_dinv(const int* __restrict__ nstart, const int* __restrict__ nlist,
                       const int* __restrict__ estart, float* __restrict__ dinv) {
    int n = blockIdx.x * blockDim.x + threadIdx.x;
    if (n >= Nn) return;
    int s = nstart[n], e = nstart[n + 1];
    float sum = 0.f;
    for (int j = s; j < e; j++) {
        int ed = nlist[j];
        sum += (float)(estart[ed + 1] - estart[ed]);
    }
    dinv[n] = (sum > 0.f) ? 1.f / sum : 1.f;
}

// ---------------- convert helpers ----------------
__device__ __forceinline__ uint4 pack8(const float* f) {
    uint4 u;
    __half2 h0 = __float22half2_rn(make_float2(f[0], f[1]));
    __half2 h1 = __float22half2_rn(make_float2(f[2], f[3]));
    __half2 h2 = __float22half2_rn(make_float2(f[4], f[5]));
    __half2 h3 = __float22half2_rn(make_float2(f[6], f[7]));
    u.x = *(unsigned*)&h0; u.y = *(unsigned*)&h1;
    u.z = *(unsigned*)&h2; u.w = *(unsigned*)&h3;
    return u;
}

__global__ void k_cvtX(const float* __restrict__ src, uint4* __restrict__ dst) {
    int i = blockIdx.x * blockDim.x + threadIdx.x;
    if (i >= Nn * FT / 8) return;
    float f[8];
    *(float4*)&f[0] = *(const float4*)(src + (size_t)i * 8);
    *(float4*)&f[4] = *(const float4*)(src + (size_t)i * 8 + 4);
    dst[i] = pack8(f);
}

__global__ void k_bnrelu_cvt(const float* __restrict__ src, const float* __restrict__ bn,
                             uint4* __restrict__ dst) {
    int i = blockIdx.x * blockDim.x + threadIdx.x;
    if (i >= Nn * HID / 8) return;
    int c8 = (i & 31) * 8;
    float f[8], sc[8], sh[8];
    *(float4*)&f[0] = *(const float4*)(src + (size_t)i * 8);
    *(float4*)&f[4] = *(const float4*)(src + (size_t)i * 8 + 4);
    *(float4*)&sc[0] = *(const float4*)(bn + c8);
    *(float4*)&sc[4] = *(const float4*)(bn + c8 + 4);
    *(float4*)&sh[0] = *(const float4*)(bn + HID + c8);
    *(float4*)&sh[4] = *(const float4*)(bn + HID + c8 + 4);
#pragma unroll
    for (int j = 0; j < 8; j++) f[j] = fmaxf(f[j] * sc[j] + sh[j], 0.f);
    dst[i] = pack8(f);
}

// ---------------- fp16 CSR segment-sum gather ----------------
template <int D, bool OUT_HALF>
__global__ void k_gath(const uint4* __restrict__ src, const int* __restrict__ start,
                       const int* __restrict__ list, void* __restrict__ dst, int rows) {
    int row = (blockIdx.x * blockDim.x + threadIdx.x) >> 5;
    int lane = threadIdx.x & 31;
    if (row >= rows) return;
    int s = __ldg(&start[row]), e = __ldg(&start[row + 1]);
    float acc[8] = {};
    if (D == 256) {
        for (int j0 = s; j0 < e; j0 += 32) {
            int cnt = min(32, e - j0);
            int id = (lane < cnt) ? __ldg(&list[j0 + lane]) : 0;
            for (int jj = 0; jj < cnt; jj++) {
                int r = __shfl_sync(0xffffffffu, id, jj);
                uint4 v = __ldg(&src[(size_t)r * 32 + lane]);
                const __half2* h = (const __half2*)&v;
#pragma unroll
                for (int q = 0; q < 4; q++) {
                    float2 f = __half22float2(h[q]);
                    acc[2 * q] += f.x;
                    acc[2 * q + 1] += f.y;
                }
            }
        }
    } else {
        int oct = lane & 15, par = lane >> 4;
        for (int j0 = s; j0 < e; j0 += 32) {
            int cnt = min(32, e - j0);
            int id = (lane < cnt) ? __ldg(&list[j0 + lane]) : 0;
            for (int jj = 0; jj < cnt; jj += 2) {
                int r0 = __shfl_sync(0xffffffffu, id, jj);
                int r1 = (jj + 1 < cnt) ? __shfl_sync(0xffffffffu, id, jj + 1) : -1;
                int r = par ? r1 : r0;
                if (r >= 0) {
                    uint4 v = __ldg(&src[(size_t)r * 16 + oct]);
                    const __half2* h = (const __half2*)&v;
#pragma unroll
                    for (int q = 0; q < 4; q++) {
                        float2 f = __half22float2(h[q]);
                        acc[2 * q] += f.x;
                        acc[2 * q + 1] += f.y;
                    }
                }
            }
        }
#pragma unroll
        for (int q = 0; q < 8; q++) acc[q] += __shfl_xor_sync(0xffffffffu, acc[q], 16);
        if (par) return;
        lane = oct;
    }
    const int OC = D / 8;
    if (OUT_HALF) {
        ((uint4*)dst)[(size_t)row * OC + lane] = pack8(acc);
    } else {
        float* o = (float*)dst + (size_t)row * D + lane * 8;
        *(float4*)o = *(float4*)&acc[0];
        *(float4*)(o + 4) = *(float4*)&acc[4];
    }
}

// ---------------- bf16x3 tensor-core GEMM + fused BN stats ----------------
__device__ __forceinline__ void bfsplit(float v, unsigned short& h, float& lo) {
    __nv_bfloat16 b = __float2bfloat16_rn(v);
    h = *(unsigned short*)&b;
    lo = v - __bfloat162float(b);
}
__device__ __forceinline__ unsigned short bf16o(float v) {
    __nv_bfloat16 b = __float2bfloat16_rn(v);
    return *(unsigned short*)&b;
}
__device__ __forceinline__ void mma16(float* c, const unsigned* a, unsigned b0, unsigned b1) {
    asm volatile(
        "mma.sync.aligned.m16n8k16.row.col.f32.bf16.bf16.f32 "
        "{%0,%1,%2,%3}, {%4,%5,%6,%7}, {%8,%9}, {%0,%1,%2,%3};"
        : "+f"(c[0]), "+f"(c[1]), "+f"(c[2]), "+f"(c[3])
        : "r"(a[0]), "r"(a[1]), "r"(a[2]), "r"(a[3]), "r"(b0), "r"(b1));
}

// C = act(A) @ B + bias, block tile 128x128, 256 thr, 8 warps (4m x 2n), warp 32x64.
// A/B split into bf16 hi/lo; 3 mma passes: hi*hi + lo*hi + hi*lo.
template <bool BNA>
__global__ __launch_bounds__(256) void k_gemm_tc(
    const float* __restrict__ A, const float* __restrict__ B,
    const float* __restrict__ bias, const float* __restrict__ bn,
    float* __restrict__ C, float* __restrict__ stats, int K, int Nc, int Mrows) {
    // [k-pair][row/col], pair packs (k even, k odd) bf16
    __shared__ unsigned Ah[8][132], Al[8][132];
    __shared__ unsigned Bh[8][132], Bl[8][132];
    __shared__ float shS[128], shQ[128];
    const int t = threadIdx.x;
    const int wid = t >> 5, lane = t & 31;
    const int wm = wid & 3, wn = wid >> 2;
    const int g = lane >> 2, tg = lane & 3;
    const int row0 = blockIdx.y * 128, col0 = blockIdx.x * 128;

    float acc[2][8][4];
#pragma unroll
    for (int i = 0; i < 2; i++)
#pragma unroll
        for (int j = 0; j < 8; j++)
#pragma unroll
            for (int r = 0; r < 4; r++) acc[i][j][r] = 0.f;

    const int ar = t >> 1;          // A fill row
    const int ak = (t & 1) * 8;     // A k offset 0/8
    const int kp = t >> 5;          // B fill k-pair 0..7
    const int bc = (lane) * 4;      // B col offset 0..124

    for (int kb = 0; kb < K; kb += 16) {
        // ---- A 128x16 -> hi/lo pairs ----
#pragma unroll
        for (int q = 0; q < 2; q++) {
            float4 v = *(const float4*)(A + (size_t)(row0 + ar) * K + kb + ak + q * 4);
            if (BNA) {
                float4 sc = *(const float4*)(bn + kb + ak + q * 4);
                float4 sh = *(const float4*)(bn + HID + kb + ak + q * 4);
                v.x = fmaxf(v.x * sc.x + sh.x, 0.f);
                v.y = fmaxf(v.y * sc.y + sh.y, 0.f);
                v.z = fmaxf(v.z * sc.z + sh.z, 0.f);
                v.w = fmaxf(v.w * sc.w + sh.w, 0.f);
            }
            float vv[4] = {v.x, v.y, v.z, v.w};
            unsigned short h[4];
            float lo[4];
#pragma unroll
            for (int j = 0; j < 4; j++) bfsplit(vv[j], h[j], lo[j]);
            int p0 = (ak >> 1) + 2 * q;
            Ah[p0][ar] = (unsigned)h[0] | ((unsigned)h[1] << 16);
            Ah[p0 + 1][ar] = (unsigned)h[2] | ((unsigned)h[3] << 16);
            Al[p0][ar] = (unsigned)bf16o(lo[0]) | ((unsigned)bf16o(lo[1]) << 16);
            Al[p0 + 1][ar] = (unsigned)bf16o(lo[2]) | ((unsigned)bf16o(lo[3]) << 16);
        }
        // ---- B 16x128 -> hi/lo pairs (pair spans two k rows) ----
        {
            float4 r0 = *(const float4*)(B + (size_t)(kb + 2 * kp) * Nc + col0 + bc);
            float4 r1 = *(const float4*)(B + (size_t)(kb + 2 * kp + 1) * Nc + col0 + bc);
            float e0[4] = {r0.x, r0.y, r0.z, r0.w};
            float e1[4] = {r1.x, r1.y, r1.z, r1.w};
#pragma unroll
            for (int j = 0; j < 4; j++) {
                unsigned short h0, h1;
                float l0, l1;
                bfsplit(e0[j], h0, l0);
                bfsplit(e1[j], h1, l1);
                Bh[kp][bc + j] = (unsigned)h0 | ((unsigned)h1 << 16);
                Bl[kp][bc + j] = (unsigned)bf16o(l0) | ((unsigned)bf16o(l1) << 16);
            }
        }
        __syncthreads();

        // ---- fragments + mma ----
        unsigned ah[2][4], al[2][4];
#pragma unroll
        for (int mt = 0; mt < 2; mt++) {
            int rm = wm * 32 + mt * 16 + g;
            ah[mt][0] = Ah[tg][rm];     ah[mt][1] = Ah[tg][rm + 8];
            ah[mt][2] = Ah[tg + 4][rm]; ah[mt][3] = Ah[tg + 4][rm + 8];
            al[mt][0] = Al[tg][rm];     al[mt][1] = Al[tg][rm + 8];
            al[mt][2] = Al[tg + 4][rm]; al[mt][3] = Al[tg + 4][rm + 8];
        }
#pragma unroll
        for (int nt = 0; nt < 8; nt++) {
            int n = wn * 64 + nt * 8 + g;
            unsigned bh0 = Bh[tg][n], bh1 = Bh[tg + 4][n];
            unsigned bl0 = Bl[tg][n], bl1 = Bl[tg + 4][n];
#pragma unroll
            for (int mt = 0; mt < 2; mt++) {
                mma16(acc[mt][nt], ah[mt], bh0, bh1);
                mma16(acc[mt][nt], al[mt], bh0, bh1);
                mma16(acc[mt][nt], ah[mt], bl0, bl1);
            }
        }
        __syncthreads();
    }

    // ---- epilogue: write C + BN stats for valid rows ----
    if (t < 128) { shS[t] = 0.f; shQ[t] = 0.f; }
    __syncthreads();

    float colS[16] = {}, colQ[16] = {};
#pragma unroll
    for (int nt = 0; nt < 8; nt++) {
        int c = col0 + wn * 64 + nt * 8 + 2 * tg;
        float2 bb = *(const float2*)&bias[c];
#pragma unroll
        for (int mt = 0; mt < 2; mt++) {
            int r = row0 + wm * 32 + mt * 16 + g;
            float v0 = acc[mt][nt][0] + bb.x, v1 = acc[mt][nt][1] + bb.y;
            float v2 = acc[mt][nt][2] + bb.x, v3 = acc[mt][nt][3] + bb.y;
            if (r < Mrows) {
                *(float2*)(C + (size_t)r * Nc + c) = make_float2(v0, v1);
                colS[nt * 2] += v0; colQ[nt * 2] += v0 * v0;
                colS[nt * 2 + 1] += v1; colQ[nt * 2 + 1] += v1 * v1;
            }
            if (r + 8 < Mrows) {
                *(float2*)(C + (size_t)(r + 8) * Nc + c) = make_float2(v2, v3);
                colS[nt * 2] += v2; colQ[nt * 2] += v2 * v2;
                colS[nt * 2 + 1] += v3; colQ[nt * 2 + 1] += v3 * v3;
            }
        }
    }
#pragma unroll
    for (int off = 4; off <= 16; off <<= 1)
#pragma unroll
        for (int i = 0; i < 16; i++) {
            colS[i] += __shfl_xor_sync(0xffffffffu, colS[i], off);
            colQ[i] += __shfl_xor_sync(0xffffffffu, colQ[i], off);
        }
    if (g == 0) {
#pragma unroll
        for (int i = 0; i < 16; i++) {
            int cc = wn * 64 + (i >> 1) * 8 + 2 * tg + (i & 1);
            atomicAdd(&shS[cc], colS[i]);
            atomicAdd(&shQ[cc], colQ[i]);
        }
    }
    __syncthreads();
    if (t < 128) {
        atomicAdd(&stats[col0 + t], shS[t]);
        atomicAdd(&stats[HID + col0 + t], shQ[t]);
    }
}

// ---------------- BN params ----------------
__global__ void k_bnparams(float* __restrict__ stats, const float* __restrict__ g,
                           const float* __restrict__ b, float* __restrict__ bn) {
    int c = threadIdx.x;
    float mean = stats[c] * (1.f / Nn);
    float var = stats[HID + c] * (1.f / Nn) - mean * mean;
    float sc = g[c] * rsqrtf(var + BN_EPS);
    bn[c] = sc;
    bn[HID + c] = b[c] - mean * sc;
    stats[c] = 0.f;
    stats[HID + c] = 0.f;
}

// ---------------- fused head + segment accumulation ----------------
__global__ void k_head_seg(const float* __restrict__ p0, const float* __restrict__ p1,
                           const float* __restrict__ dinv, const int* __restrict__ batch,
                           const float* __restrict__ W, const float* __restrict__ hb,
                           float* __restrict__ ssum, float* __restrict__ scnt) {
    int wid = (blockIdx.x * blockDim.x + threadIdx.x) >> 5;
    int lane = threadIdx.x & 31;
    if (wid >= Nn) return;
    float acc[NCLS] = {};
    const float* r0 = p0 + (size_t)wid * HID;
    const float* r1 = p1 + (size_t)wid * HID;
    for (int k = lane; k < HID; k += 32) {
        float v = r0[k];
        const float* w = W + (size_t)k * NCLS;
#pragma unroll
        for (int c = 0; c < NCLS; c++) acc[c] += v * w[c];
        float v2 = r1[k];
        const float* w2 = W + (size_t)(HID + k) * NCLS;
#pragma unroll
        for (int c = 0; c < NCLS; c++) acc[c] += v2 * w2[c];
    }
#pragma unroll
    for (int o = 16; o > 0; o >>= 1)
#pragma unroll
        for (int c = 0; c < NCLS; c++) acc[c] += __shfl_down_sync(0xffffffffu, acc[c], o);
    if (lane == 0) {
        float d = dinv[wid];
        int b = batch[wid];
        atomicAdd(&scnt[b], 1.f);
#pragma unroll
        for (int c = 0; c < NCLS; c++)
            atomicAdd(&ssum[b * NCLS + c], acc[c] * d + hb[c]);
    }
}

__global__ void k_fin(const float* __restrict__ ssum, const float* __restrict__ scnt,
                      float* __restrict__ dout) {
    int t = blockIdx.x * blockDim.x + threadIdx.x;
    if (t < NG * NCLS) {
        int gidx = t / NCLS;
        dout[t] = ssum[t] / fmaxf(scnt[gidx], 1.f);
    }
}

// ---------------- host ----------------
extern "C" void kernel_launch(void* const* d_in, const int* in_sizes, int n_in,
                              void* d_out, int out_size) {
    const float* X = (const float*)d_in[0];
    const int* node_idx = (const int*)d_in[1];
    const int* edge_idx = (const int*)d_in[2];
    const int* all_batch = (const int*)d_in[3];
    const float* W1_0 = (const float*)d_in[4];
    const float* b1_0 = (const float*)d_in[5];
    const float* g1_0 = (const float*)d_in[6];
    const float* be1_0 = (const float*)d_in[7];
    const float* W2_0 = (const float*)d_in[8];
    const float* b2_0 = (const float*)d_in[9];
    const float* bng_0 = (const float*)d_in[10];
    const float* bnb_0 = (const float*)d_in[11];
    const float* W1_1 = (const float*)d_in[12];
    const float* b1_1 = (const float*)d_in[13];
    const float* g1_1 = (const float*)d_in[14];
    const float* be1_1 = (const float*)d_in[15];
    const float* W2_1 = (const float*)d_in[16];
    const float* b2_1 = (const float*)d_in[17];
    const float* bng_1 = (const float*)d_in[18];
    const float* bnb_1 = (const float*)d_in[19];
    const float* head_W = (const float*)d_in[20];
    const float* head_b = (const float*)d_in[21];

    float *P0, *P1, *Z, *h0, *h1, *dinv, *stats, *bn, *ssum, *scnt;
    __half *Xh, *hh, *Eh;
    int *ecnt, *estart, *ecur, *elist, *ncnt, *nstart, *ncur, *nlist;
    cudaGetSymbolAddress((void**)&P0, g_P0);
    cudaGetSymbolAddress((void**)&P1, g_P1);
    cudaGetSymbolAddress((void**)&Z, g_Z);
    cudaGetSymbolAddress((void**)&h0, g_h0);
    cudaGetSymbolAddress((void**)&h1, g_h1);
    cudaGetSymbolAddress((void**)&Xh, g_Xh);
    cudaGetSymbolAddress((void**)&hh, g_hh);
    cudaGetSymbolAddress((void**)&Eh, g_Eh);
    cudaGetSymbolAddress((void**)&dinv, g_dinv);
    cudaGetSymbolAddress((void**)&stats, g_stats);
    cudaGetSymbolAddress((void**)&bn, g_bn);
    cudaGetSymbolAddress((void**)&ssum, g_segsum);
    cudaGetSymbolAddress((void**)&scnt, g_segcnt);
    cudaGetSymbolAddress((void**)&ecnt, g_ecnt);
    cudaGetSymbolAddress((void**)&estart, g_estart);
    cudaGetSymbolAddress((void**)&ecur, g_ecur);
    cudaGetSymbolAddress((void**)&elist, g_elist);
    cudaGetSymbolAddress((void**)&ncnt, g_ncnt);
    cudaGetSymbolAddress((void**)&nstart, g_nstart);
    cudaGetSymbolAddress((void**)&ncur, g_ncur);
    cudaGetSymbolAddress((void**)&nlist, g_nlist);

    const int SB = 256;
    const int nnz_blocks = (NNZv + SB - 1) / SB;
    const int ge = (Mm * 32 + SB - 1) / SB;
    const int gn = (Nn * 32 + SB - 1) / SB;
    dim3 tc_grid(HID / 128, NPAD / 128);

    // ---- CSR build ----
    k_init<<<64, SB>>>(ecnt, ncnt, stats, ssum, scnt);
    k_hist<<<nnz_blocks, SB>>>(node_idx, edge_idx, ecnt, ncnt);
    k_scan2<<<2, 1024>>>(ecnt, estart, ecur, ncnt, nstart, ncur);
    k_fill<<<nnz_blocks, SB>>>(node_idx, edge_idx, ecur, elist, ncur, nlist);
    k_dinv<<<(Nn + SB - 1) / SB, SB>>>(nstart, nlist, estart, dinv);

    // ---- layer 0 (Pa in P1 buffer, [N,128]) ----
    k_cvtX<<<(Nn * FT / 8 + SB - 1) / SB, SB>>>(X, (uint4*)Xh);
    k_gath<128, true><<<ge, SB>>>((const uint4*)Xh, estart, elist, Eh, Mm);
    k_gath<128, false><<<gn, SB>>>((const uint4*)Eh, nstart, nlist, P1, Nn);
    k_gemm_tc<false><<<tc_grid, 256>>>(P1, W1_0, b1_0, bn, Z, stats, FT, HID, Nn);
    k_bnparams<<<1, HID>>>(stats, g1_0, be1_0, bn);
    k_gemm_tc<true><<<tc_grid, 256>>>(Z, W2_0, b2_0, bn, h0, stats, HID, HID, Nn);
    k_bnparams<<<1, HID>>>(stats, bng_0, bnb_0, bn);

    // ---- layer 1 (P0 = H(Ht(bn(h0))), reused for head) ----
    k_bnrelu_cvt<<<(Nn * HID / 8 + SB - 1) / SB, SB>>>(h0, bn, (uint4*)hh);
    k_gath<256, true><<<ge, SB>>>((const uint4*)hh, estart, elist, Eh, Mm);
    k_gath<256, false><<<gn, SB>>>((const uint4*)Eh, nstart, nlist, P0, Nn);
    k_gemm_tc<false><<<tc_grid, 256>>>(P0, W1_1, b1_1, bn, Z, stats, HID, HID, Nn);
    k_bnparams<<<1, HID>>>(stats, g1_1, be1_1, bn);
    k_gemm_tc<true><<<tc_grid, 256>>>(Z, W2_1, b2_1, bn, h1, stats, HID, HID, Nn);
    k_bnparams<<<1, HID>>>(stats, bng_1, bnb_1, bn);

    // ---- pooling for h1 ----
    k_bnrelu_cvt<<<(Nn * HID / 8 + SB - 1) / SB, SB>>>(h1, bn, (uint4*)hh);
    k_gath<256, true><<<ge, SB>>>((const uint4*)hh, estart, elist, Eh, Mm);
    k_gath<256, false><<<gn, SB>>>((const uint4*)Eh, nstart, nlist, P1, Nn);

    // ---- fused head + readout ----
    k_head_seg<<<(Nn * 32 + SB - 1) / SB, SB>>>(P0, P1, dinv, all_batch, head_W, head_b, ssum, scnt);
    k_fin<<<(NG * NCLS + SB - 1) / SB, SB>>>(ssum, scnt, (float*)d_out);
}

// round 8
// speedup vs baseline: 1.2380x; 1.0020x over previous
#include <cuda_runtime.h>
#include <cuda_fp16.h>
#include <cuda_bf16.h>

#define Nn 40000
#define NPAD 40064
#define Mm 10000
#define NNZv 400000
#define FT 128
#define HID 256
#define NCLS 10
#define NG 128
#define BN_EPS 1e-5f

// ---------------- scratch ----------------
__device__ float g_P0[(size_t)NPAD * HID];        // fp32 pooled h0 (head input)
__device__ float g_P1[(size_t)NPAD * HID];        // fp32 pooled h1 (head input)
__device__ float g_Z[(size_t)NPAD * HID];
__device__ float g_h0[(size_t)NPAD * HID];
__device__ float g_h1[(size_t)NPAD * HID];
__device__ unsigned g_Ah[(size_t)NPAD * 128];     // A hi, packed bf16 k-pairs
__device__ unsigned g_Al[(size_t)NPAD * 128];     // A lo
__device__ unsigned g_Wh[114688];                 // pre-split weights hi (4 mats)
__device__ unsigned g_Wl[114688];                 // lo
__device__ __half g_Xh[(size_t)Nn * FT];
__device__ __half g_hh[(size_t)Nn * HID];
__device__ __half g_Eh[(size_t)Mm * HID];
__device__ float g_dinv[Nn];
__device__ float g_stats[2 * HID];
__device__ float g_bn[2 * HID];
__device__ float g_segsum[NG * NCLS];
__device__ float g_segcnt[NG];
__device__ int g_ecnt[Mm];
__device__ int g_estart[Mm + 1];
__device__ int g_ecur[Mm];
__device__ int g_elist[NNZv];
__device__ int g_ncnt[Nn];
__device__ int g_nstart[Nn + 1];
__device__ int g_ncur[Nn];
__device__ int g_nlist[NNZv];

// weight offsets in g_Wh/g_Wl (unsigned units): W1_0, W2_0, W1_1, W2_1
#define OFF_W10 0
#define OFF_W20 16384
#define OFF_W11 49152
#define OFF_W21 81920

// ---------------- bf16 helpers ----------------
__device__ __forceinline__ unsigned bfpack2(float a, float b) {
    __nv_bfloat162 h;
    h.x = __float2bfloat16_rn(a);
    h.y = __float2bfloat16_rn(b);
    return *(unsigned*)&h;
}
// split 8 floats (channels 2j,2j+1 -> pair j) into hi/lo packed uint4
__device__ __forceinline__ void split8(const float* f, uint4& hi, uint4& lo) {
    unsigned h[4], l[4];
#pragma unroll
    for (int j = 0; j < 4; j++) {
        float a = f[2 * j], b = f[2 * j + 1];
        __nv_bfloat16 ba = __float2bfloat16_rn(a), bb = __float2bfloat16_rn(b);
        h[j] = (unsigned)(*(unsigned short*)&ba) | ((unsigned)(*(unsigned short*)&bb) << 16);
        l[j] = bfpack2(a - __bfloat162float(ba), b - __bfloat162float(bb));
    }
    hi = make_uint4(h[0], h[1], h[2], h[3]);
    lo = make_uint4(l[0], l[1], l[2], l[3]);
}

// ---------------- init / utility ----------------
__global__ void k_init(int* ecnt, int* ncnt, float* stats, float* ssum, float* scnt) {
    int i = blockIdx.x * blockDim.x + threadIdx.x;
    int stride = gridDim.x * blockDim.x;
    for (int j = i; j < Mm; j += stride) ecnt[j] = 0;
    for (int j = i; j < Nn; j += stride) ncnt[j] = 0;
    if (i < 2 * HID) stats[i] = 0.f;
    if (i < NG * NCLS) ssum[i] = 0.f;
    if (i < NG) scnt[i] = 0.f;
}

// pre-split one weight matrix [K x Nc] into packed k-pair hi/lo
__global__ void k_wsplit(const float* __restrict__ W, int K, int Nc,
                         unsigned* __restrict__ oh, unsigned* __restrict__ ol) {
    int idx = blockIdx.x * blockDim.x + threadIdx.x;
    int total = (K / 2) * Nc;
    if (idx >= total) return;
    int kp = idx / Nc, c = idx % Nc;
    float a = W[(size_t)(2 * kp) * Nc + c];
    float b = W[(size_t)(2 * kp + 1) * Nc + c];
    __nv_bfloat16 ba = __float2bfloat16_rn(a), bb = __float2bfloat16_rn(b);
    oh[idx] = (unsigned)(*(unsigned short*)&ba) | ((unsigned)(*(unsigned short*)&bb) << 16);
    ol[idx] = bfpack2(a - __bfloat162float(ba), b - __bfloat162float(bb));
}

// ---------------- CSR build ----------------
__global__ void k_hist(const int* __restrict__ nidx, const int* __restrict__ eidx,
                       int* __restrict__ ecnt, int* __restrict__ ncnt) {
    int i = blockIdx.x * blockDim.x + threadIdx.x;
    if (i < NNZv) {
        atomicAdd(&ecnt[eidx[i]], 1);
        atomicAdd(&ncnt[nidx[i]], 1);
    }
}

__global__ void k_scan2(const int* __restrict__ ecnt, int* __restrict__ estart, int* __restrict__ ecur,
                        const int* __restrict__ ncnt, int* __restrict__ nstart, int* __restrict__ ncur) {
    const int* cnt = blockIdx.x ? ncnt : ecnt;
    int* start = blockIdx.x ? nstart : estart;
    int* cursor = blockIdx.x ? ncur : ecur;
    int n = blockIdx.x ? Nn : Mm;
    __shared__ int buf[1024];
    __shared__ int carry;
    int t = threadIdx.x;
    if (t == 0) carry = 0;
    __syncthreads();
    for (int base = 0; base < n; base += 1024) {
        int v = (base + t < n) ? cnt[base + t] : 0;
        buf[t] = v;
        __syncthreads();
        for (int off = 1; off < 1024; off <<= 1) {
            int x = (t >= off) ? buf[t - off] : 0;
            __syncthreads();
            buf[t] += x;
            __syncthreads();
        }
        int excl = buf[t] - v + carry;
        if (base + t < n) { start[base + t] = excl; cursor[base + t] = excl; }
        __syncthreads();
        if (t == 1023) carry += buf[1023];
        __syncthreads();
    }
    if (t == 0) start[n] = carry;
}

__global__ void k_fill(const int* __restrict__ nidx, const int* __restrict__ eidx,
                       int* __restrict__ ecur, int* __restrict__ elist,
                       int* __restrict__ ncur, int* __restrict__ nlist) {
    int i = blockIdx.x * blockDim.x + threadIdx.x;
    if (i < NNZv) {
        int e = eidx[i], n = nidx[i];
        elist[atomicAdd(&ecur[e], 1)] = n;
        nlist[atomicAdd(&ncur[n], 1)] = e;
    }
}

__global__ void k_dinv(const int* __restrict__ nstart, const int* __restrict__ nlist,
                       const int* __restrict__ estart, float* __restrict__ dinv) {
    int n = blockIdx.x * blockDim.x + threadIdx.x;
    if (n >= Nn) return;
    int s = nstart[n], e = nstart[n + 1];
    float sum = 0.f;
    for (int j = s; j < e; j++) {
        int ed = nlist[j];
        sum += (float)(estart[ed + 1] - estart[ed]);
    }
    dinv[n] = (sum > 0.f) ? 1.f / sum : 1.f;
}

// ---------------- convert helpers ----------------
__device__ __forceinline__ uint4 pack8h(const float* f) {
    uint4 u;
    __half2 h0 = __float22half2_rn(make_float2(f[0], f[1]));
    __half2 h1 = __float22half2_rn(make_float2(f[2], f[3]));
    __half2 h2 = __float22half2_rn(make_float2(f[4], f[5]));
    __half2 h3 = __float22half2_rn(make_float2(f[6], f[7]));
    u.x = *(unsigned*)&h0; u.y = *(unsigned*)&h1;
    u.z = *(unsigned*)&h2; u.w = *(unsigned*)&h3;
    return u;
}

__global__ void k_cvtX(const float* __restrict__ src, uint4* __restrict__ dst) {
    int i = blockIdx.x * blockDim.x + threadIdx.x;
    if (i >= Nn * FT / 8) return;
    float f[8];
    *(float4*)&f[0] = *(const float4*)(src + (size_t)i * 8);
    *(float4*)&f[4] = *(const float4*)(src + (size_t)i * 8 + 4);
    dst[i] = pack8h(f);
}

// h fp32 + bn -> relu fp16 (gather source)
__global__ void k_bnrelu_cvt(const float* __restrict__ src, const float* __restrict__ bn,
                             uint4* __restrict__ dst) {
    int i = blockIdx.x * blockDim.x + threadIdx.x;
    if (i >= Nn * HID / 8) return;
    int c8 = (i & 31) * 8;
    float f[8], sc[8], sh[8];
    *(float4*)&f[0] = *(const float4*)(src + (size_t)i * 8);
    *(float4*)&f[4] = *(const float4*)(src + (size_t)i * 8 + 4);
    *(float4*)&sc[0] = *(const float4*)(bn + c8);
    *(float4*)&sc[4] = *(const float4*)(bn + c8 + 4);
    *(float4*)&sh[0] = *(const float4*)(bn + HID + c8);
    *(float4*)&sh[4] = *(const float4*)(bn + HID + c8 + 4);
#pragma unroll
    for (int j = 0; j < 8; j++) f[j] = fmaxf(f[j] * sc[j] + sh[j], 0.f);
    dst[i] = pack8h(f);
}

// Z fp32 + bn -> relu, split to packed bf16 hi/lo (GEMM A source)
__global__ void k_bnsplit(const float* __restrict__ src, const float* __restrict__ bn,
                          uint4* __restrict__ ah, uint4* __restrict__ al) {
    int i = blockIdx.x * blockDim.x + threadIdx.x;
    if (i >= Nn * HID / 8) return;
    int c8 = (i & 31) * 8;
    float f[8], sc[8], sh[8];
    *(float4*)&f[0] = *(const float4*)(src + (size_t)i * 8);
    *(float4*)&f[4] = *(const float4*)(src + (size_t)i * 8 + 4);
    *(float4*)&sc[0] = *(const float4*)(bn + c8);
    *(float4*)&sc[4] = *(const float4*)(bn + c8 + 4);
    *(float4*)&sh[0] = *(const float4*)(bn + HID + c8);
    *(float4*)&sh[4] = *(const float4*)(bn + HID + c8 + 4);
#pragma unroll
    for (int j = 0; j < 8; j++) f[j] = fmaxf(f[j] * sc[j] + sh[j], 0.f);
    uint4 hi, lo;
    split8(f, hi, lo);
    ah[i] = hi;
    al[i] = lo;
}

// ---------------- fp16 CSR segment-sum gather ----------------
// MODE: 0 = fp16 out, 1 = bf16 hi/lo out, 2 = bf16 hi/lo + fp32 out, 3 = fp32 out
template <int D, int MODE>
__global__ void k_gath(const uint4* __restrict__ src, const int* __restrict__ start,
                       const int* __restrict__ list, void* __restrict__ d0,
                       void* __restrict__ d1, void* __restrict__ d2, int rows) {
    int row = (blockIdx.x * blockDim.x + threadIdx.x) >> 5;
    int lane = threadIdx.x & 31;
    if (row >= rows) return;
    int s = __ldg(&start[row]), e = __ldg(&start[row + 1]);
    float acc[8] = {};
    if (D == 256) {
        for (int j0 = s; j0 < e; j0 += 32) {
            int cnt = min(32, e - j0);
            int id = (lane < cnt) ? __ldg(&list[j0 + lane]) : 0;
            for (int jj = 0; jj < cnt; jj++) {
                int r = __shfl_sync(0xffffffffu, id, jj);
                uint4 v = __ldg(&src[(size_t)r * 32 + lane]);
                const __half2* h = (const __half2*)&v;
#pragma unroll
                for (int q = 0; q < 4; q++) {
                    float2 f = __half22float2(h[q]);
                    acc[2 * q] += f.x;
                    acc[2 * q + 1] += f.y;
                }
            }
        }
    } else {
        int oct = lane & 15, par = lane >> 4;
        for (int j0 = s; j0 < e; j0 += 32) {
            int cnt = min(32, e - j0);
            int id = (lane < cnt) ? __ldg(&list[j0 + lane]) : 0;
            for (int jj = 0; jj < cnt; jj += 2) {
                int r0 = __shfl_sync(0xffffffffu, id, jj);
                int r1 = (jj + 1 < cnt) ? __shfl_sync(0xffffffffu, id, jj + 1) : -1;
                int r = par ? r1 : r0;
                if (r >= 0) {
                    uint4 v = __ldg(&src[(size_t)r * 16 + oct]);
                    const __half2* h = (const __half2*)&v;
#pragma unroll
                    for (int q = 0; q < 4; q++) {
                        float2 f = __half22float2(h[q]);
                        acc[2 * q] += f.x;
                        acc[2 * q + 1] += f.y;
                    }
                }
            }
        }
#pragma unroll
        for (int q = 0; q < 8; q++) acc[q] += __shfl_xor_sync(0xffffffffu, acc[q], 16);
        if (par) return;
        lane = oct;
    }
    const int OC = D / 8;  // uint4 per row
    if (MODE == 0) {
        ((uint4*)d0)[(size_t)row * OC + lane] = pack8h(acc);
    } else if (MODE == 1 || MODE == 2) {
        uint4 hi, lo;
        split8(acc, hi, lo);
        ((uint4*)d0)[(size_t)row * OC + lane] = hi;
        ((uint4*)d1)[(size_t)row * OC + lane] = lo;
        if (MODE == 2) {
            float* o = (float*)d2 + (size_t)row * D + lane * 8;
            *(float4*)o = *(float4*)&acc[0];
            *(float4*)(o + 4) = *(float4*)&acc[4];
        }
    } else {
        float* o = (float*)d0 + (size_t)row * D + lane * 8;
        *(float4*)o = *(float4*)&acc[0];
        *(float4*)(o + 4) = *(float4*)&acc[4];
    }
}

// ---------------- bf16x3 tensor-core GEMM (pre-split operands) ----------------
__device__ __forceinline__ void mma16(float* c, const unsigned* a, unsigned b0, unsigned b1) {
    asm volatile(
        "mma.sync.aligned.m16n8k16.row.col.f32.bf16.bf16.f32 "
        "{%0,%1,%2,%3}, {%4,%5,%6,%7}, {%8,%9}, {%0,%1,%2,%3};"
        : "+f"(c[0]), "+f"(c[1]), "+f"(c[2]), "+f"(c[3])
        : "r"(a[0]), "r"(a[1]), "r"(a[2]), "r"(a[3]), "r"(b0), "r"(b1));
}

// C = A @ B + bias; A given as packed bf16 hi/lo [rows x K/2], B as [K/2 x Nc] packed.
__global__ __launch_bounds__(256) void k_gemm_tc(
    const unsigned* __restrict__ Ahg, const unsigned* __restrict__ Alg,
    const unsigned* __restrict__ Bhg, const unsigned* __restrict__ Blg,
    const float* __restrict__ bias, float* __restrict__ C,
    float* __restrict__ stats, int K, int Nc, int Mrows) {
    __shared__ unsigned Ah[8][132], Al[8][132];
    __shared__ unsigned Bh[8][132], Bl[8][132];
    __shared__ float shS[128], shQ[128];
    const int t = threadIdx.x;
    const int wid = t >> 5, lane = t & 31;
    const int wm = wid & 3, wn = wid >> 2;
    const int g = lane >> 2, tg = lane & 3;
    const int row0 = blockIdx.y * 128, col0 = blockIdx.x * 128;
    const int Kp = K / 2;

    float acc[2][8][4];
#pragma unroll
    for (int i = 0; i < 2; i++)
#pragma unroll
        for (int j = 0; j < 8; j++)
#pragma unroll
            for (int r = 0; r < 4; r++) acc[i][j][r] = 0.f;

    const int ar = t >> 1;          // A fill row
    const int ap = (t & 1) * 4;     // A k-pair offset 0/4
    const int kp = t >> 5;          // B fill k-pair 0..7

    for (int kb = 0; kb < Kp; kb += 8) {
        // A: 128 rows x 8 pairs
        {
            uint4 hi = *(const uint4*)(Ahg + (size_t)(row0 + ar) * Kp + kb + ap);
            uint4 lo = *(const uint4*)(Alg + (size_t)(row0 + ar) * Kp + kb + ap);
            Ah[ap + 0][ar] = hi.x; Ah[ap + 1][ar] = hi.y;
            Ah[ap + 2][ar] = hi.z; Ah[ap + 3][ar] = hi.w;
            Al[ap + 0][ar] = lo.x; Al[ap + 1][ar] = lo.y;
            Al[ap + 2][ar] = lo.z; Al[ap + 3][ar] = lo.w;
        }
        // B: 8 pairs x 128 cols
        {
            uint4 hi = *(const uint4*)(Bhg + (size_t)(kb + kp) * Nc + col0 + lane * 4);
            uint4 lo = *(const uint4*)(Blg + (size_t)(kb + kp) * Nc + col0 + lane * 4);
            *(uint4*)&Bh[kp][lane * 4] = hi;
            *(uint4*)&Bl[kp][lane * 4] = lo;
        }
        __syncthreads();

        unsigned ah[2][4], al[2][4];
#pragma unroll
        for (int mt = 0; mt < 2; mt++) {
            int rm = wm * 32 + mt * 16 + g;
            ah[mt][0] = Ah[tg][rm];     ah[mt][1] = Ah[tg][rm + 8];
            ah[mt][2] = Ah[tg + 4][rm]; ah[mt][3] = Ah[tg + 4][rm + 8];
            al[mt][0] = Al[tg][rm];     al[mt][1] = Al[tg][rm + 8];
            al[mt][2] = Al[tg + 4][rm]; al[mt][3] = Al[tg + 4][rm + 8];
        }
#pragma unroll
        for (int nt = 0; nt < 8; nt++) {
            int n = wn * 64 + nt * 8 + g;
            unsigned bh0 = Bh[tg][n], bh1 = Bh[tg + 4][n];
            unsigned bl0 = Bl[tg][n], bl1 = Bl[tg + 4][n];
#pragma unroll
            for (int mt = 0; mt < 2; mt++) {
                mma16(acc[mt][nt], ah[mt], bh0, bh1);
                mma16(acc[mt][nt], al[mt], bh0, bh1);
                mma16(acc[mt][nt], ah[mt], bl0, bl1);
            }
        }
        __syncthreads();
    }

    // ---- epilogue ----
    if (t < 128) { shS[t] = 0.f; shQ[t] = 0.f; }
    __syncthreads();

    float colS[16] = {}, colQ[16] = {};
#pragma unroll
    for (int nt = 0; nt < 8; nt++) {
        int c = col0 + wn * 64 + nt * 8 + 2 * tg;
        float2 bb = *(const float2*)&bias[c];
#pragma unroll
        for (int mt = 0; mt < 2; mt++) {
            int r = row0 + wm * 32 + mt * 16 + g;
            float v0 = acc[mt][nt][0] + bb.x, v1 = acc[mt][nt][1] + bb.y;
            float v2 = acc[mt][nt][2] + bb.x, v3 = acc[mt][nt][3] + bb.y;
            if (r < Mrows) {
                *(float2*)(C + (size_t)r * Nc + c) = make_float2(v0, v1);
                colS[nt * 2] += v0; colQ[nt * 2] += v0 * v0;
                colS[nt * 2 + 1] += v1; colQ[nt * 2 + 1] += v1 * v1;
            }
            if (r + 8 < Mrows) {
                *(float2*)(C + (size_t)(r + 8) * Nc + c) = make_float2(v2, v3);
                colS[nt * 2] += v2; colQ[nt * 2] += v2 * v2;
                colS[nt * 2 + 1] += v3; colQ[nt * 2 + 1] += v3 * v3;
            }
        }
    }
#pragma unroll
    for (int off = 4; off <= 16; off <<= 1)
#pragma unroll
        for (int i = 0; i < 16; i++) {
            colS[i] += __shfl_xor_sync(0xffffffffu, colS[i], off);
            colQ[i] += __shfl_xor_sync(0xffffffffu, colQ[i], off);
        }
    if (g == 0) {
#pragma unroll
        for (int i = 0; i < 16; i++) {
            int cc = wn * 64 + (i >> 1) * 8 + 2 * tg + (i & 1);
            atomicAdd(&shS[cc], colS[i]);
            atomicAdd(&shQ[cc], colQ[i]);
        }
    }
    __syncthreads();
    if (t < 128) {
        atomicAdd(&stats[col0 + t], shS[t]);
        atomicAdd(&stats[HID + col0 + t], shQ[t]);
    }
}

// ---------------- BN params ----------------
__global__ void k_bnparams(float* __restrict__ stats, const float* __restrict__ g,
                           const float* __restrict__ b, float* __restrict__ bn) {
    int c = threadIdx.x;
    float mean = stats[c] * (1.f / Nn);
    float var = stats[HID + c] * (1.f / Nn) - mean * mean;
    float sc = g[c] * rsqrtf(var + BN_EPS);
    bn[c] = sc;
    bn[HID + c] = b[c] - mean * sc;
    stats[c] = 0.f;
    stats[HID + c] = 0.f;
}

// ---------------- fused head + segment accumulation ----------------
__global__ void k_head_seg(const float* __restrict__ p0, const float* __restrict__ p1,
                           const float* __restrict__ dinv, const int* __restrict__ batch,
                           const float* __restrict__ W, const float* __restrict__ hb,
                           float* __restrict__ ssum, float* __restrict__ scnt) {
    int wid = (blockIdx.x * blockDim.x + threadIdx.x) >> 5;
    int lane = threadIdx.x & 31;
    if (wid >= Nn) return;
    float acc[NCLS] = {};
    const float* r0 = p0 + (size_t)wid * HID;
    const float* r1 = p1 + (size_t)wid * HID;
    for (int k = lane; k < HID; k += 32) {
        float v = r0[k];
        const float* w = W + (size_t)k * NCLS;
#pragma unroll
        for (int c = 0; c < NCLS; c++) acc[c] += v * w[c];
        float v2 = r1[k];
        const float* w2 = W + (size_t)(HID + k) * NCLS;
#pragma unroll
        for (int c = 0; c < NCLS; c++) acc[c] += v2 * w2[c];
    }
#pragma unroll
    for (int o = 16; o > 0; o >>= 1)
#pragma unroll
        for (int c = 0; c < NCLS; c++) acc[c] += __shfl_down_sync(0xffffffffu, acc[c], o);
    if (lane == 0) {
        float d = dinv[wid];
        int b = batch[wid];
        atomicAdd(&scnt[b], 1.f);
#pragma unroll
        for (int c = 0; c < NCLS; c++)
            atomicAdd(&ssum[b * NCLS + c], acc[c] * d + hb[c]);
    }
}

__global__ void k_fin(const float* __restrict__ ssum, const float* __restrict__ scnt,
                      float* __restrict__ dout) {
    int t = blockIdx.x * blockDim.x + threadIdx.x;
    if (t < NG * NCLS) {
        int gidx = t / NCLS;
        dout[t] = ssum[t] / fmaxf(scnt[gidx], 1.f);
    }
}

// ---------------- host ----------------
extern "C" void kernel_launch(void* const* d_in, const int* in_sizes, int n_in,
                              void* d_out, int out_size) {
    const float* X = (const float*)d_in[0];
    const int* node_idx = (const int*)d_in[1];
    const int* edge_idx = (const int*)d_in[2];
    const int* all_batch = (const int*)d_in[3];
    const float* W1_0 = (const float*)d_in[4];
    const float* b1_0 = (const float*)d_in[5];
    const float* g1_0 = (const float*)d_in[6];
    const float* be1_0 = (const float*)d_in[7];
    const float* W2_0 = (const float*)d_in[8];
    const float* b2_0 = (const float*)d_in[9];
    const float* bng_0 = (const float*)d_in[10];
    const float* bnb_0 = (const float*)d_in[11];
    const float* W1_1 = (const float*)d_in[12];
    const float* b1_1 = (const float*)d_in[13];
    const float* g1_1 = (const float*)d_in[14];
    const float* be1_1 = (const float*)d_in[15];
    const float* W2_1 = (const float*)d_in[16];
    const float* b2_1 = (const float*)d_in[17];
    const float* bng_1 = (const float*)d_in[18];
    const float* bnb_1 = (const float*)d_in[19];
    const float* head_W = (const float*)d_in[20];
    const float* head_b = (const float*)d_in[21];

    float *P0, *P1, *Z, *h0, *h1, *dinv, *stats, *bn, *ssum, *scnt;
    unsigned *Ah, *Al, *Wh, *Wl;
    __half *Xh, *hh, *Eh;
    int *ecnt, *estart, *ecur, *elist, *ncnt, *nstart, *ncur, *nlist;
    cudaGetSymbolAddress((void**)&P0, g_P0);
    cudaGetSymbolAddress((void**)&P1, g_P1);
    cudaGetSymbolAddress((void**)&Z, g_Z);
    cudaGetSymbolAddress((void**)&h0, g_h0);
    cudaGetSymbolAddress((void**)&h1, g_h1);
    cudaGetSymbolAddress((void**)&Ah, g_Ah);
    cudaGetSymbolAddress((void**)&Al, g_Al);
    cudaGetSymbolAddress((void**)&Wh, g_Wh);
    cudaGetSymbolAddress((void**)&Wl, g_Wl);
    cudaGetSymbolAddress((void**)&Xh, g_Xh);
    cudaGetSymbolAddress((void**)&hh, g_hh);
    cudaGetSymbolAddress((void**)&Eh, g_Eh);
    cudaGetSymbolAddress((void**)&dinv, g_dinv);
    cudaGetSymbolAddress((void**)&stats, g_stats);
    cudaGetSymbolAddress((void**)&bn, g_bn);
    cudaGetSymbolAddress((void**)&ssum, g_segsum);
    cudaGetSymbolAddress((void**)&scnt, g_segcnt);
    cudaGetSymbolAddress((void**)&ecnt, g_ecnt);
    cudaGetSymbolAddress((void**)&estart, g_estart);
    cudaGetSymbolAddress((void**)&ecur, g_ecur);
    cudaGetSymbolAddress((void**)&elist, g_elist);
    cudaGetSymbolAddress((void**)&ncnt, g_ncnt);
    cudaGetSymbolAddress((void**)&nstart, g_nstart);
    cudaGetSymbolAddress((void**)&ncur, g_ncur);
    cudaGetSymbolAddress((void**)&nlist, g_nlist);

    const int SB = 256;
    const int nnz_blocks = (NNZv + SB - 1) / SB;
    const int ge = (Mm * 32 + SB - 1) / SB;
    const int gn = (Nn * 32 + SB - 1) / SB;
    dim3 tc_grid(HID / 128, NPAD / 128);

    // ---- CSR build + weight pre-split ----
    k_init<<<64, SB>>>(ecnt, ncnt, stats, ssum, scnt);
    k_wsplit<<<(16384 + SB - 1) / SB, SB>>>(W1_0, FT, HID, Wh + OFF_W10, Wl + OFF_W10);
    k_wsplit<<<(32768 + SB - 1) / SB, SB>>>(W2_0, HID, HID, Wh + OFF_W20, Wl + OFF_W20);
    k_wsplit<<<(32768 + SB - 1) / SB, SB>>>(W1_1, HID, HID, Wh + OFF_W11, Wl + OFF_W11);
    k_wsplit<<<(32768 + SB - 1) / SB, SB>>>(W2_1, HID, HID, Wh + OFF_W21, Wl + OFF_W21);
    k_hist<<<nnz_blocks, SB>>>(node_idx, edge_idx, ecnt, ncnt);
    k_scan2<<<2, 1024>>>(ecnt, estart, ecur, ncnt, nstart, ncur);
    k_fill<<<nnz_blocks, SB>>>(node_idx, edge_idx, ecur, elist, ncur, nlist);
    k_dinv<<<(Nn + SB - 1) / SB, SB>>>(nstart, nlist, estart, dinv);

    // ---- layer 0 ----
    k_cvtX<<<(Nn * FT / 8 + SB - 1) / SB, SB>>>(X, (uint4*)Xh);
    k_gath<128, 0><<<ge, SB>>>((const uint4*)Xh, estart, elist, Eh, 0, 0, Mm);
    k_gath<128, 1><<<gn, SB>>>((const uint4*)Eh, nstart, nlist, Ah, Al, 0, Nn);
    k_gemm_tc<<<tc_grid, 256>>>(Ah, Al, Wh + OFF_W10, Wl + OFF_W10, b1_0, Z, stats, FT, HID, Nn);
    k_bnparams<<<1, HID>>>(stats, g1_0, be1_0, bn);
    k_bnsplit<<<(Nn * HID / 8 + SB - 1) / SB, SB>>>(Z, bn, (uint4*)Ah, (uint4*)Al);
    k_gemm_tc<<<tc_grid, 256>>>(Ah, Al, Wh + OFF_W20, Wl + OFF_W20, b2_0, h0, stats, HID, HID, Nn);
    k_bnparams<<<1, HID>>>(stats, bng_0, bnb_0, bn);

    // ---- layer 1 ----
    k_bnrelu_cvt<<<(Nn * HID / 8 + SB - 1) / SB, SB>>>(h0, bn, (uint4*)hh);
    k_gath<256, 0><<<ge, SB>>>((const uint4*)hh, estart, elist, Eh, 0, 0, Mm);
    k_gath<256, 2><<<gn, SB>>>((const uint4*)Eh, nstart, nlist, Ah, Al, P0, Nn);
    k_gemm_tc<<<tc_grid, 256>>>(Ah, Al, Wh + OFF_W11, Wl + OFF_W11, b1_1, Z, stats, HID, HID, Nn);
    k_bnparams<<<1, HID>>>(stats, g1_1, be1_1, bn);
    k_bnsplit<<<(Nn * HID / 8 + SB - 1) / SB, SB>>>(Z, bn, (uint4*)Ah, (uint4*)Al);
    k_gemm_tc<<<tc_grid, 256>>>(Ah, Al, Wh + OFF_W21, Wl + OFF_W21, b2_1, h1, stats, HID, HID, Nn);
    k_bnparams<<<1, HID>>>(stats, bng_1, bnb_1, bn);

    // ---- pooling for h1 ----
    k_bnrelu_cvt<<<(Nn * HID / 8 + SB - 1) / SB, SB>>>(h1, bn, (uint4*)hh);
    k_gath<256, 0><<<ge, SB>>>((const uint4*)hh, estart, elist, Eh, 0, 0, Mm);
    k_gath<256, 3><<<gn, SB>>>((const uint4*)Eh, nstart, nlist, P1, 0, 0, Nn);

    // ---- fused head + readout ----
    k_head_seg<<<(Nn * 32 + SB - 1) / SB, SB>>>(P0, P1, dinv, all_batch, head_W, head_b, ssum, scnt);
    k_fin<<<(NG * NCLS + SB - 1) / SB, SB>>>(ssum, scnt, (float*)d_out);
}

// round 9
// speedup vs baseline: 1.4662x; 1.1843x over previous
#include <cuda_runtime.h>
#include <cuda_fp16.h>

#define Nn 40000
#define NPAD 40064
#define Mm 10000
#define NNZv 400000
#define FT 128
#define HID 256
#define NCLS 10
#define NG 128
#define BN_EPS 1e-5f

// ---------------- scratch ----------------
__device__ float g_P0[(size_t)NPAD * HID];        // fp32 pooled h0 (head input)
__device__ float g_P1[(size_t)NPAD * HID];        // fp32 pooled h1 (head input)
__device__ float g_Z[(size_t)NPAD * HID];
__device__ float g_h0[(size_t)NPAD * HID];
__device__ float g_h1[(size_t)NPAD * HID];
__device__ unsigned g_A[(size_t)NPAD * 128];      // GEMM A: packed fp16 k-pairs
__device__ unsigned g_W[114688];                  // packed fp16 weights (4 mats)
__device__ __half g_Xh[(size_t)Nn * FT];
__device__ __half g_hh[(size_t)Nn * HID];
__device__ __half g_Eh[(size_t)Mm * HID];
__device__ float g_dinv[Nn];
__device__ float g_stats[2 * HID];
__device__ float g_bn[2 * HID];
__device__ float g_segsum[NG * NCLS];
__device__ float g_segcnt[NG];
__device__ int g_ecnt[Mm];
__device__ int g_estart[Mm + 1];
__device__ int g_ecur[Mm];
__device__ int g_elist[NNZv];
__device__ int g_ncnt[Nn];
__device__ int g_nstart[Nn + 1];
__device__ int g_ncur[Nn];
__device__ int g_nlist[NNZv];

#define OFF_W10 0
#define OFF_W20 16384
#define OFF_W11 49152
#define OFF_W21 81920

// ---------------- init / utility ----------------
__global__ void k_init(int* ecnt, int* ncnt, float* stats, float* ssum, float* scnt) {
    int i = blockIdx.x * blockDim.x + threadIdx.x;
    int stride = gridDim.x * blockDim.x;
    for (int j = i; j < Mm; j += stride) ecnt[j] = 0;
    for (int j = i; j < Nn; j += stride) ncnt[j] = 0;
    if (i < 2 * HID) stats[i] = 0.f;
    if (i < NG * NCLS) ssum[i] = 0.f;
    if (i < NG) scnt[i] = 0.f;
}

// pack one weight matrix [K x Nc] into fp16 k-pairs
__global__ void k_wsplit(const float* __restrict__ W, int K, int Nc,
                         unsigned* __restrict__ oh) {
    int idx = blockIdx.x * blockDim.x + threadIdx.x;
    int total = (K / 2) * Nc;
    if (idx >= total) return;
    int kp = idx / Nc, c = idx % Nc;
    __half2 h = __floats2half2_rn(W[(size_t)(2 * kp) * Nc + c],
                                  W[(size_t)(2 * kp + 1) * Nc + c]);
    oh[idx] = *(unsigned*)&h;
}

// ---------------- CSR build ----------------
__global__ void k_hist(const int* __restrict__ nidx, const int* __restrict__ eidx,
                       int* __restrict__ ecnt, int* __restrict__ ncnt) {
    int i = blockIdx.x * blockDim.x + threadIdx.x;
    if (i < NNZv) {
        atomicAdd(&ecnt[eidx[i]], 1);
        atomicAdd(&ncnt[nidx[i]], 1);
    }
}

__global__ void k_scan2(const int* __restrict__ ecnt, int* __restrict__ estart, int* __restrict__ ecur,
                        const int* __restrict__ ncnt, int* __restrict__ nstart, int* __restrict__ ncur) {
    const int* cnt = blockIdx.x ? ncnt : ecnt;
    int* start = blockIdx.x ? nstart : estart;
    int* cursor = blockIdx.x ? ncur : ecur;
    int n = blockIdx.x ? Nn : Mm;
    __shared__ int buf[1024];
    __shared__ int carry;
    int t = threadIdx.x;
    if (t == 0) carry = 0;
    __syncthreads();
    for (int base = 0; base < n; base += 1024) {
        int v = (base + t < n) ? cnt[base + t] : 0;
        buf[t] = v;
        __syncthreads();
        for (int off = 1; off < 1024; off <<= 1) {
            int x = (t >= off) ? buf[t - off] : 0;
            __syncthreads();
            buf[t] += x;
            __syncthreads();
        }
        int excl = buf[t] - v + carry;
        if (base + t < n) { start[base + t] = excl; cursor[base + t] = excl; }
        __syncthreads();
        if (t == 1023) carry += buf[1023];
        __syncthreads();
    }
    if (t == 0) start[n] = carry;
}

__global__ void k_fill(const int* __restrict__ nidx, const int* __restrict__ eidx,
                       int* __restrict__ ecur, int* __restrict__ elist,
                       int* __restrict__ ncur, int* __restrict__ nlist) {
    int i = blockIdx.x * blockDim.x + threadIdx.x;
    if (i < NNZv) {
        int e = eidx[i], n = nidx[i];
        elist[atomicAdd(&ecur[e], 1)] = n;
        nlist[atomicAdd(&ncur[n], 1)] = e;
    }
}

__global__ void k_dinv(const int* __restrict__ nstart, const int* __restrict__ nlist,
                       const int* __restrict__ estart, float* __restrict__ dinv) {
    int n = blockIdx.x * blockDim.x + threadIdx.x;
    if (n >= Nn) return;
    int s = nstart[n], e = nstart[n + 1];
    float sum = 0.f;
    for (int j = s; j < e; j++) {
        int ed = nlist[j];
        sum += (float)(estart[ed + 1] - estart[ed]);
    }
    dinv[n] = (sum > 0.f) ? 1.f / sum : 1.f;
}

// ---------------- convert helpers ----------------
__device__ __forceinline__ uint4 pack8h(const float* f) {
    uint4 u;
    __half2 h0 = __float22half2_rn(make_float2(f[0], f[1]));
    __half2 h1 = __float22half2_rn(make_float2(f[2], f[3]));
    __half2 h2 = __float22half2_rn(make_float2(f[4], f[5]));
    __half2 h3 = __float22half2_rn(make_float2(f[6], f[7]));
    u.x = *(unsigned*)&h0; u.y = *(unsigned*)&h1;
    u.z = *(unsigned*)&h2; u.w = *(unsigned*)&h3;
    return u;
}

__global__ void k_cvtX(const float* __restrict__ src, uint4* __restrict__ dst) {
    int i = blockIdx.x * blockDim.x + threadIdx.x;
    if (i >= Nn * FT / 8) return;
    float f[8];
    *(float4*)&f[0] = *(const float4*)(src + (size_t)i * 8);
    *(float4*)&f[4] = *(const float4*)(src + (size_t)i * 8 + 4);
    dst[i] = pack8h(f);
}

// h fp32 + bn -> relu fp16 (serves gather source AND GEMM A)
__global__ void k_bnrelu_cvt(const float* __restrict__ src, const float* __restrict__ bn,
                             uint4* __restrict__ dst) {
    int i = blockIdx.x * blockDim.x + threadIdx.x;
    if (i >= Nn * HID / 8) return;
    int c8 = (i & 31) * 8;
    float f[8], sc[8], sh[8];
    *(float4*)&f[0] = *(const float4*)(src + (size_t)i * 8);
    *(float4*)&f[4] = *(const float4*)(src + (size_t)i * 8 + 4);
    *(float4*)&sc[0] = *(const float4*)(bn + c8);
    *(float4*)&sc[4] = *(const float4*)(bn + c8 + 4);
    *(float4*)&sh[0] = *(const float4*)(bn + HID + c8);
    *(float4*)&sh[4] = *(const float4*)(bn + HID + c8 + 4);
#pragma unroll
    for (int j = 0; j < 8; j++) f[j] = fmaxf(f[j] * sc[j] + sh[j], 0.f);
    dst[i] = pack8h(f);
}

// ---------------- fp16 CSR segment-sum gather ----------------
// MODE: 0 = fp16 out (d0), 2 = fp16 out (d0) + fp32 out (d1), 3 = fp32 out (d0)
template <int D, int MODE>
__global__ void k_gath(const uint4* __restrict__ src, const int* __restrict__ start,
                       const int* __restrict__ list, void* __restrict__ d0,
                       void* __restrict__ d1, int rows) {
    int row = (blockIdx.x * blockDim.x + threadIdx.x) >> 5;
    int lane = threadIdx.x & 31;
    if (row >= rows) return;
    int s = __ldg(&start[row]), e = __ldg(&start[row + 1]);
    float acc[8] = {};
    if (D == 256) {
        for (int j0 = s; j0 < e; j0 += 32) {
            int cnt = min(32, e - j0);
            int id = (lane < cnt) ? __ldg(&list[j0 + lane]) : 0;
            for (int jj = 0; jj < cnt; jj++) {
                int r = __shfl_sync(0xffffffffu, id, jj);
                uint4 v = __ldg(&src[(size_t)r * 32 + lane]);
                const __half2* h = (const __half2*)&v;
#pragma unroll
                for (int q = 0; q < 4; q++) {
                    float2 f = __half22float2(h[q]);
                    acc[2 * q] += f.x;
                    acc[2 * q + 1] += f.y;
                }
            }
        }
    } else {
        int oct = lane & 15, par = lane >> 4;
        for (int j0 = s; j0 < e; j0 += 32) {
            int cnt = min(32, e - j0);
            int id = (lane < cnt) ? __ldg(&list[j0 + lane]) : 0;
            for (int jj = 0; jj < cnt; jj += 2) {
                int r0 = __shfl_sync(0xffffffffu, id, jj);
                int r1 = (jj + 1 < cnt) ? __shfl_sync(0xffffffffu, id, jj + 1) : -1;
                int r = par ? r1 : r0;
                if (r >= 0) {
                    uint4 v = __ldg(&src[(size_t)r * 16 + oct]);
                    const __half2* h = (const __half2*)&v;
#pragma unroll
                    for (int q = 0; q < 4; q++) {
                        float2 f = __half22float2(h[q]);
                        acc[2 * q] += f.x;
                        acc[2 * q + 1] += f.y;
                    }
                }
            }
        }
#pragma unroll
        for (int q = 0; q < 8; q++) acc[q] += __shfl_xor_sync(0xffffffffu, acc[q], 16);
        if (par) return;
        lane = oct;
    }
    const int OC = D / 8;
    if (MODE == 0 || MODE == 2) {
        ((uint4*)d0)[(size_t)row * OC + lane] = pack8h(acc);
        if (MODE == 2) {
            float* o = (float*)d1 + (size_t)row * D + lane * 8;
            *(float4*)o = *(float4*)&acc[0];
            *(float4*)(o + 4) = *(float4*)&acc[4];
        }
    } else {
        float* o = (float*)d0 + (size_t)row * D + lane * 8;
        *(float4*)o = *(float4*)&acc[0];
        *(float4*)(o + 4) = *(float4*)&acc[4];
    }
}

// ---------------- fp16 single-pass tensor-core GEMM + fused BN stats ----------------
__device__ __forceinline__ void mma16f(float* c, const unsigned* a, unsigned b0, unsigned b1) {
    asm volatile(
        "mma.sync.aligned.m16n8k16.row.col.f32.f16.f16.f32 "
        "{%0,%1,%2,%3}, {%4,%5,%6,%7}, {%8,%9}, {%0,%1,%2,%3};"
        : "+f"(c[0]), "+f"(c[1]), "+f"(c[2]), "+f"(c[3])
        : "r"(a[0]), "r"(a[1]), "r"(a[2]), "r"(a[3]), "r"(b0), "r"(b1));
}

// C = A @ B + bias; A packed fp16 k-pairs [rows x K/2], B packed [K/2 x Nc].
__global__ __launch_bounds__(256) void k_gemm_tc(
    const unsigned* __restrict__ Ag, const unsigned* __restrict__ Bg,
    const float* __restrict__ bias, float* __restrict__ C,
    float* __restrict__ stats, int K, int Nc, int Mrows) {
    __shared__ unsigned As[8][132];
    __shared__ unsigned Bs[8][132];
    __shared__ float shS[128], shQ[128];
    const int t = threadIdx.x;
    const int wid = t >> 5, lane = t & 31;
    const int wm = wid & 3, wn = wid >> 2;
    const int g = lane >> 2, tg = lane & 3;
    const int row0 = blockIdx.y * 128, col0 = blockIdx.x * 128;
    const int Kp = K / 2;

    float acc[2][8][4];
#pragma unroll
    for (int i = 0; i < 2; i++)
#pragma unroll
        for (int j = 0; j < 8; j++)
#pragma unroll
            for (int r = 0; r < 4; r++) acc[i][j][r] = 0.f;

    const int ar = t >> 1;          // A fill row
    const int ap = (t & 1) * 4;     // A k-pair offset 0/4
    const int kp = t >> 5;          // B fill k-pair 0..7

    for (int kb = 0; kb < Kp; kb += 8) {
        {
            uint4 hi = *(const uint4*)(Ag + (size_t)(row0 + ar) * Kp + kb + ap);
            As[ap + 0][ar] = hi.x; As[ap + 1][ar] = hi.y;
            As[ap + 2][ar] = hi.z; As[ap + 3][ar] = hi.w;
        }
        {
            uint4 hi = *(const uint4*)(Bg + (size_t)(kb + kp) * Nc + col0 + lane * 4);
            *(uint4*)&Bs[kp][lane * 4] = hi;
        }
        __syncthreads();

        unsigned ah[2][4];
#pragma unroll
        for (int mt = 0; mt < 2; mt++) {
            int rm = wm * 32 + mt * 16 + g;
            ah[mt][0] = As[tg][rm];     ah[mt][1] = As[tg][rm + 8];
            ah[mt][2] = As[tg + 4][rm]; ah[mt][3] = As[tg + 4][rm + 8];
        }
#pragma unroll
        for (int nt = 0; nt < 8; nt++) {
            int n = wn * 64 + nt * 8 + g;
            unsigned b0 = Bs[tg][n], b1 = Bs[tg + 4][n];
#pragma unroll
            for (int mt = 0; mt < 2; mt++) mma16f(acc[mt][nt], ah[mt], b0, b1);
        }
        __syncthreads();
    }

    // ---- epilogue: write C + BN stats for valid rows ----
    if (t < 128) { shS[t] = 0.f; shQ[t] = 0.f; }
    __syncthreads();

    float colS[16] = {}, colQ[16] = {};
#pragma unroll
    for (int nt = 0; nt < 8; nt++) {
        int c = col0 + wn * 64 + nt * 8 + 2 * tg;
        float2 bb = *(const float2*)&bias[c];
#pragma unroll
        for (int mt = 0; mt < 2; mt++) {
            int r = row0 + wm * 32 + mt * 16 + g;
            float v0 = acc[mt][nt][0] + bb.x, v1 = acc[mt][nt][1] + bb.y;
            float v2 = acc[mt][nt][2] + bb.x, v3 = acc[mt][nt][3] + bb.y;
            if (r < Mrows) {
                *(float2*)(C + (size_t)r * Nc + c) = make_float2(v0, v1);
                colS[nt * 2] += v0; colQ[nt * 2] += v0 * v0;
                colS[nt * 2 + 1] += v1; colQ[nt * 2 + 1] += v1 * v1;
            }
            if (r + 8 < Mrows) {
                *(float2*)(C + (size_t)(r + 8) * Nc + c) = make_float2(v2, v3);
                colS[nt * 2] += v2; colQ[nt * 2] += v2 * v2;
                colS[nt * 2 + 1] += v3; colQ[nt * 2 + 1] += v3 * v3;
            }
        }
    }
#pragma unroll
    for (int off = 4; off <= 16; off <<= 1)
#pragma unroll
        for (int i = 0; i < 16; i++) {
            colS[i] += __shfl_xor_sync(0xffffffffu, colS[i], off);
            colQ[i] += __shfl_xor_sync(0xffffffffu, colQ[i], off);
        }
    if (g == 0) {
#pragma unroll
        for (int i = 0; i < 16; i++) {
            int cc = wn * 64 + (i >> 1) * 8 + 2 * tg + (i & 1);
            atomicAdd(&shS[cc], colS[i]);
            atomicAdd(&shQ[cc], colQ[i]);
        }
    }
    __syncthreads();
    if (t < 128) {
        atomicAdd(&stats[col0 + t], shS[t]);
        atomicAdd(&stats[HID + col0 + t], shQ[t]);
    }
}

// ---------------- BN params ----------------
__global__ void k_bnparams(float* __restrict__ stats, const float* __restrict__ g,
                           const float* __restrict__ b, float* __restrict__ bn) {
    int c = threadIdx.x;
    float mean = stats[c] * (1.f / Nn);
    float var = stats[HID + c] * (1.f / Nn) - mean * mean;
    float sc = g[c] * rsqrtf(var + BN_EPS);
    bn[c] = sc;
    bn[HID + c] = b[c] - mean * sc;
    stats[c] = 0.f;
    stats[HID + c] = 0.f;
}

// ---------------- fused head + segment accumulation ----------------
__global__ void k_head_seg(const float* __restrict__ p0, const float* __restrict__ p1,
                           const float* __restrict__ dinv, const int* __restrict__ batch,
                           const float* __restrict__ W, const float* __restrict__ hb,
                           float* __restrict__ ssum, float* __restrict__ scnt) {
    int wid = (blockIdx.x * blockDim.x + threadIdx.x) >> 5;
    int lane = threadIdx.x & 31;
    if (wid >= Nn) return;
    float acc[NCLS] = {};
    const float* r0 = p0 + (size_t)wid * HID;
    const float* r1 = p1 + (size_t)wid * HID;
    for (int k = lane; k < HID; k += 32) {
        float v = r0[k];
        const float* w = W + (size_t)k * NCLS;
#pragma unroll
        for (int c = 0; c < NCLS; c++) acc[c] += v * w[c];
        float v2 = r1[k];
        const float* w2 = W + (size_t)(HID + k) * NCLS;
#pragma unroll
        for (int c = 0; c < NCLS; c++) acc[c] += v2 * w2[c];
    }
#pragma unroll
    for (int o = 16; o > 0; o >>= 1)
#pragma unroll
        for (int c = 0; c < NCLS; c++) acc[c] += __shfl_down_sync(0xffffffffu, acc[c], o);
    if (lane == 0) {
        float d = dinv[wid];
        int b = batch[wid];
        atomicAdd(&scnt[b], 1.f);
#pragma unroll
        for (int c = 0; c < NCLS; c++)
            atomicAdd(&ssum[b * NCLS + c], acc[c] * d + hb[c]);
    }
}

__global__ void k_fin(const float* __restrict__ ssum, const float* __restrict__ scnt,
                      float* __restrict__ dout) {
    int t = blockIdx.x * blockDim.x + threadIdx.x;
    if (t < NG * NCLS) {
        int gidx = t / NCLS;
        dout[t] = ssum[t] / fmaxf(scnt[gidx], 1.f);
    }
}

// ---------------- host ----------------
extern "C" void kernel_launch(void* const* d_in, const int* in_sizes, int n_in,
                              void* d_out, int out_size) {
    const float* X = (const float*)d_in[0];
    const int* node_idx = (const int*)d_in[1];
    const int* edge_idx = (const int*)d_in[2];
    const int* all_batch = (const int*)d_in[3];
    const float* W1_0 = (const float*)d_in[4];
    const float* b1_0 = (const float*)d_in[5];
    const float* g1_0 = (const float*)d_in[6];
    const float* be1_0 = (const float*)d_in[7];
    const float* W2_0 = (const float*)d_in[8];
    const float* b2_0 = (const float*)d_in[9];
    const float* bng_0 = (const float*)d_in[10];
    const float* bnb_0 = (const float*)d_in[11];
    const float* W1_1 = (const float*)d_in[12];
    const float* b1_1 = (const float*)d_in[13];
    const float* g1_1 = (const float*)d_in[14];
    const float* be1_1 = (const float*)d_in[15];
    const float* W2_1 = (const float*)d_in[16];
    const float* b2_1 = (const float*)d_in[17];
    const float* bng_1 = (const float*)d_in[18];
    const float* bnb_1 = (const float*)d_in[19];
    const float* head_W = (const float*)d_in[20];
    const float* head_b = (const float*)d_in[21];

    float *P0, *P1, *Z, *h0, *h1, *dinv, *stats, *bn, *ssum, *scnt;
    unsigned *A, *W;
    __half *Xh, *hh, *Eh;
    int *ecnt, *estart, *ecur, *elist, *ncnt, *nstart, *ncur, *nlist;
    cudaGetSymbolAddress((void**)&P0, g_P0);
    cudaGetSymbolAddress((void**)&P1, g_P1);
    cudaGetSymbolAddress((void**)&Z, g_Z);
    cudaGetSymbolAddress((void**)&h0, g_h0);
    cudaGetSymbolAddress((void**)&h1, g_h1);
    cudaGetSymbolAddress((void**)&A, g_A);
    cudaGetSymbolAddress((void**)&W, g_W);
    cudaGetSymbolAddress((void**)&Xh, g_Xh);
    cudaGetSymbolAddress((void**)&hh, g_hh);
    cudaGetSymbolAddress((void**)&Eh, g_Eh);
    cudaGetSymbolAddress((void**)&dinv, g_dinv);
    cudaGetSymbolAddress((void**)&stats, g_stats);
    cudaGetSymbolAddress((void**)&bn, g_bn);
    cudaGetSymbolAddress((void**)&ssum, g_segsum);
    cudaGetSymbolAddress((void**)&scnt, g_segcnt);
    cudaGetSymbolAddress((void**)&ecnt, g_ecnt);
    cudaGetSymbolAddress((void**)&estart, g_estart);
    cudaGetSymbolAddress((void**)&ecur, g_ecur);
    cudaGetSymbolAddress((void**)&elist, g_elist);
    cudaGetSymbolAddress((void**)&ncnt, g_ncnt);
    cudaGetSymbolAddress((void**)&nstart, g_nstart);
    cudaGetSymbolAddress((void**)&ncur, g_ncur);
    cudaGetSymbolAddress((void**)&nlist, g_nlist);

    const int SB = 256;
    const int nnz_blocks = (NNZv + SB - 1) / SB;
    const int ge = (Mm * 32 + SB - 1) / SB;
    const int gn = (Nn * 32 + SB - 1) / SB;
    dim3 tc_grid(HID / 128, NPAD / 128);

    // ---- CSR build + weight packing ----
    k_init<<<64, SB>>>(ecnt, ncnt, stats, ssum, scnt);
    k_wsplit<<<(16384 + SB - 1) / SB, SB>>>(W1_0, FT, HID, W + OFF_W10);
    k_wsplit<<<(32768 + SB - 1) / SB, SB>>>(W2_0, HID, HID, W + OFF_W20);
    k_wsplit<<<(32768 + SB - 1) / SB, SB>>>(W1_1, HID, HID, W + OFF_W11);
    k_wsplit<<<(32768 + SB - 1) / SB, SB>>>(W2_1, HID, HID, W + OFF_W21);
    k_hist<<<nnz_blocks, SB>>>(node_idx, edge_idx, ecnt, ncnt);
    k_scan2<<<2, 1024>>>(ecnt, estart, ecur, ncnt, nstart, ncur);
    k_fill<<<nnz_blocks, SB>>>(node_idx, edge_idx, ecur, elist, ncur, nlist);
    k_dinv<<<(Nn + SB - 1) / SB, SB>>>(nstart, nlist, estart, dinv);

    // ---- layer 0 ----
    k_cvtX<<<(Nn * FT / 8 + SB - 1) / SB, SB>>>(X, (uint4*)Xh);
    k_gath<128, 0><<<ge, SB>>>((const uint4*)Xh, estart, elist, Eh, 0, Mm);
    k_gath<128, 0><<<gn, SB>>>((const uint4*)Eh, nstart, nlist, A, 0, Nn);
    k_gemm_tc<<<tc_grid, 256>>>(A, W + OFF_W10, b1_0, Z, stats, FT, HID, Nn);
    k_bnparams<<<1, HID>>>(stats, g1_0, be1_0, bn);
    k_bnrelu_cvt<<<(Nn * HID / 8 + SB - 1) / SB, SB>>>(Z, bn, (uint4*)A);
    k_gemm_tc<<<tc_grid, 256>>>(A, W + OFF_W20, b2_0, h0, stats, HID, HID, Nn);
    k_bnparams<<<1, HID>>>(stats, bng_0, bnb_0, bn);

    // ---- layer 1 ----
    k_bnrelu_cvt<<<(Nn * HID / 8 + SB - 1) / SB, SB>>>(h0, bn, (uint4*)hh);
    k_gath<256, 0><<<ge, SB>>>((const uint4*)hh, estart, elist, Eh, 0, Mm);
    k_gath<256, 2><<<gn, SB>>>((const uint4*)Eh, nstart, nlist, A, P0, Nn);
    k_gemm_tc<<<tc_grid, 256>>>(A, W + OFF_W11, b1_1, Z, stats, HID, HID, Nn);
    k_bnparams<<<1, HID>>>(stats, g1_1, be1_1, bn);
    k_bnrelu_cvt<<<(Nn * HID / 8 + SB - 1) / SB, SB>>>(Z, bn, (uint4*)A);
    k_gemm_tc<<<tc_grid, 256>>>(A, W + OFF_W21, b2_1, h1, stats, HID, HID, Nn);
    k_bnparams<<<1, HID>>>(stats, bng_1, bnb_1, bn);

    // ---- pooling for h1 ----
    k_bnrelu_cvt<<<(Nn * HID / 8 + SB - 1) / SB, SB>>>(h1, bn, (uint4*)hh);
    k_gath<256, 0><<<ge, SB>>>((const uint4*)hh, estart, elist, Eh, 0, Mm);
    k_gath<256, 3><<<gn, SB>>>((const uint4*)Eh, nstart, nlist, P1, 0, Nn);

    // ---- fused head + readout ----
    k_head_seg<<<(Nn * 32 + SB - 1) / SB, SB>>>(P0, P1, dinv, all_batch, head_W, head_b, ssum, scnt);
    k_fin<<<(NG * NCLS + SB - 1) / SB, SB>>>(ssum, scnt, (float*)d_out);
}